// round 8
// baseline (speedup 1.0000x reference)
#include <cuda_runtime.h>
#include <cuda_bf16.h>
#include <math.h>
#include <stdint.h>

#define DIM    3072
#define NHEADS 24
#define HDIM   128
#define SEQ    2304

// ---------------------------------------------------------------------------
// Scratch (allocation-free: __device__ globals)
// ---------------------------------------------------------------------------
__device__ float g_q[SEQ * DIM];
__device__ float g_k[SEQ * DIM];
__device__ float g_v[SEQ * DIM];
__device__ float g_attn[SEQ * DIM];

__device__ int8_t g_x1[SEQ * DIM], g_x2[SEQ * DIM];
__device__ int8_t g_a1[SEQ * DIM], g_a2[SEQ * DIM];
__device__ int8_t g_wq1[DIM * DIM], g_wq2[DIM * DIM];
__device__ int8_t g_wk1[DIM * DIM], g_wk2[DIM * DIM];
__device__ int8_t g_wv1[DIM * DIM], g_wv2[DIM * DIM];
__device__ int8_t g_wo1[DIM * DIM], g_wo2[DIM * DIM];
__device__ float g_sx[SEQ], g_sa[SEQ];
__device__ float g_swq[DIM], g_swk[DIM], g_swv[DIM], g_swo[DIM];

__device__ __nv_bfloat16 g_qh[SEQ * DIM], g_ql[SEQ * DIM];
__device__ __nv_bfloat16 g_kh[SEQ * DIM], g_kl[SEQ * DIM];
__device__ __nv_bfloat16 g_vh[SEQ * DIM], g_vl[SEQ * DIM];

// fp32 pair -> packed bf16 hi / bf16 lo
__device__ __forceinline__ uint2 split2(float a, float b) {
    __nv_bfloat162 h = __floats2bfloat162_rn(a, b);
    __nv_bfloat162 l = __floats2bfloat162_rn(a - __bfloat162float(h.x),
                                             b - __bfloat162float(h.y));
    uint2 r;
    r.x = *reinterpret_cast<uint32_t*>(&h);
    r.y = *reinterpret_cast<uint32_t*>(&l);
    return r;
}

__device__ __forceinline__ void cp16(uint32_t saddr, const void* gptr) {
    asm volatile("cp.async.cg.shared.global [%0], [%1], 16;"
                 :: "r"(saddr), "l"(gptr));
}

__device__ __forceinline__ uint32_t lds32(uint32_t a) {
    uint32_t v;
    asm("ld.shared.b32 %0, [%1];" : "=r"(v) : "r"(a));
    return v;
}

#define MMA_S8(d, a, b)                                                       \
    asm volatile("mma.sync.aligned.m16n8k32.row.col.s32.s8.s8.s32 "           \
                 "{%0,%1,%2,%3}, {%4,%5,%6,%7}, {%8,%9}, {%0,%1,%2,%3};"      \
                 : "+r"(d[0]), "+r"(d[1]), "+r"(d[2]), "+r"(d[3])             \
                 : "r"(a[0]), "r"(a[1]), "r"(a[2]), "r"(a[3]),                \
                   "r"(b[0]), "r"(b[1]))

#define MMA_BF16(d, a, b)                                                     \
    asm volatile("mma.sync.aligned.m16n8k16.row.col.f32.bf16.bf16.f32 "       \
                 "{%0,%1,%2,%3}, {%4,%5,%6,%7}, {%8,%9}, {%0,%1,%2,%3};"      \
                 : "+f"(d[0]), "+f"(d[1]), "+f"(d[2]), "+f"(d[3])             \
                 : "r"(a[0]), "r"(a[1]), "r"(a[2]), "r"(a[3]),                \
                   "r"(b[0]), "r"(b[1]))

// ---------------------------------------------------------------------------
// Row-wise dual-limb int8 quantization: x = s*(i1 + i2/256), s = rowmax/127.
// ---------------------------------------------------------------------------
__global__ __launch_bounds__(256)
void quant8(const float* __restrict__ in, int8_t* __restrict__ o1,
            int8_t* __restrict__ o2, float* __restrict__ scale, int ncols) {
    __shared__ float red[256];
    const int row = blockIdx.x, tid = threadIdx.x;
    const float* rp = in + (size_t)row * ncols;

    float mx = 0.f;
    for (int i = tid; i < ncols; i += 256) mx = fmaxf(mx, fabsf(rp[i]));
    red[tid] = mx;
    __syncthreads();
#pragma unroll
    for (int st = 128; st > 0; st >>= 1) {
        if (tid < st) red[tid] = fmaxf(red[tid], red[tid + st]);
        __syncthreads();
    }
    const float s = fmaxf(red[0], 1e-20f) / 127.f;
    const float inv = 1.f / s;
    if (tid == 0) scale[row] = s;

    for (int i = tid; i < ncols; i += 256) {
        const float v = rp[i];
        int q1 = __float2int_rn(v * inv);
        q1 = max(-127, min(127, q1));
        const float r = v - (float)q1 * s;
        int q2 = __float2int_rn(r * inv * 256.f);
        q2 = max(-128, min(127, q2));
        o1[(size_t)row * ncols + i] = (int8_t)q1;
        o2[(size_t)row * ncols + i] = (int8_t)q2;
    }
}

// ---------------------------------------------------------------------------
// int8 dual-limb GEMM (NT): C = sa[m]*sb[n]*(A(16b) . B(16b)) + bias[n]
// BM=128, BN=64, BK=64 bytes. 256 threads = 8 warps (2M x 4N), warp 64x16.
// 4 passes per k32: i1j1 -> acc1, i1j2+i2j1 -> acc23, i2j2 -> acc4.
// cp.async double-buffered.
// ---------------------------------------------------------------------------
#define RSTR  80                    // smem row stride (64 data + 16 pad)
#define A_B   (128 * RSTR)          // 10240 per A limb
#define B_B   (64 * RSTR)           // 5120 per B limb
#define SSTAGE (2 * A_B + 2 * B_B)  // 30720

struct GemmS8Batch {
    const int8_t* B1[3];
    const int8_t* B2[3];
    const float*  sb[3];
    const float*  bias[3];
    float*        C[3];
};

__global__ __launch_bounds__(256)
void gemm_s8(const int8_t* __restrict__ A1, const int8_t* __restrict__ A2,
             const float* __restrict__ sa, GemmS8Batch bt,
             int M, int N, int K) {
    extern __shared__ uint8_t smem[];
    const uint32_t sbase = (uint32_t)__cvta_generic_to_shared(smem);

    const int8_t* __restrict__ B1 = bt.B1[blockIdx.z];
    const int8_t* __restrict__ B2 = bt.B2[blockIdx.z];
    const float* __restrict__ sbv = bt.sb[blockIdx.z];
    const float* __restrict__ bias = bt.bias[blockIdx.z];
    float* __restrict__ C = bt.C[blockIdx.z];

    const int bm = blockIdx.y * 128, bn = blockIdx.x * 64;
    const int tid = threadIdx.x;
    const int w = tid >> 5, lane = tid & 31;
    const int wm = w & 1, wn = w >> 1;          // 2M x 4N warps
    const int g = lane >> 2, tg = lane & 3;

    int acc1[4][2][4], acc23[4][2][4], acc4[4][2][4];
#pragma unroll
    for (int mi = 0; mi < 4; mi++)
#pragma unroll
        for (int ni = 0; ni < 2; ni++)
#pragma unroll
            for (int r = 0; r < 4; r++) {
                acc1[mi][ni][r] = 0; acc23[mi][ni][r] = 0; acc4[mi][ni][r] = 0;
            }

    // loader: 1536 16B chunks/stage (A1 512, A2 512, B1 256, B2 256), 6/thread
    auto issue = [&](int kt, int stage) {
        const uint32_t sb_ = sbase + (uint32_t)stage * SSTAGE;
#pragma unroll
        for (int i = 0; i < 6; i++) {
            const int c = tid + i * 256;
            if (c < 512) {
                const int r = c >> 2, q = c & 3;
                cp16(sb_ + r * RSTR + q * 16,
                     A1 + (size_t)(bm + r) * K + kt + q * 16);
            } else if (c < 1024) {
                const int cc = c - 512, r = cc >> 2, q = cc & 3;
                cp16(sb_ + A_B + r * RSTR + q * 16,
                     A2 + (size_t)(bm + r) * K + kt + q * 16);
            } else if (c < 1280) {
                const int cc = c - 1024, r = cc >> 2, q = cc & 3;
                cp16(sb_ + 2 * A_B + r * RSTR + q * 16,
                     B1 + (size_t)(bn + r) * K + kt + q * 16);
            } else {
                const int cc = c - 1280, r = cc >> 2, q = cc & 3;
                cp16(sb_ + 2 * A_B + B_B + r * RSTR + q * 16,
                     B2 + (size_t)(bn + r) * K + kt + q * 16);
            }
        }
    };

    const int ntiles = K / 64;
    issue(0, 0);
    asm volatile("cp.async.commit_group;");

    for (int t = 0; t < ntiles; t++) {
        if (t + 1 < ntiles) issue((t + 1) * 64, (t + 1) & 1);
        asm volatile("cp.async.commit_group;");
        asm volatile("cp.async.wait_group 1;");
        __syncthreads();

        const uint32_t stg = sbase + (uint32_t)(t & 1) * SSTAGE;

#pragma unroll
        for (int ks = 0; ks < 2; ks++) {
            const uint32_t kb = ks * 32 + tg * 4;
            uint32_t a1f[4][4], a2f[4][4];
#pragma unroll
            for (int mi = 0; mi < 4; mi++) {
                const uint32_t ad = stg + (wm * 64 + mi * 16 + g) * RSTR + kb;
                a1f[mi][0] = lds32(ad);
                a1f[mi][1] = lds32(ad + 8 * RSTR);
                a1f[mi][2] = lds32(ad + 16);
                a1f[mi][3] = lds32(ad + 8 * RSTR + 16);
                a2f[mi][0] = lds32(ad + A_B);
                a2f[mi][1] = lds32(ad + A_B + 8 * RSTR);
                a2f[mi][2] = lds32(ad + A_B + 16);
                a2f[mi][3] = lds32(ad + A_B + 8 * RSTR + 16);
            }
            uint32_t b1f[2][2], b2f[2][2];
#pragma unroll
            for (int ni = 0; ni < 2; ni++) {
                const uint32_t bd = stg + 2 * A_B + (wn * 16 + ni * 8 + g) * RSTR + kb;
                b1f[ni][0] = lds32(bd);
                b1f[ni][1] = lds32(bd + 16);
                b2f[ni][0] = lds32(bd + B_B);
                b2f[ni][1] = lds32(bd + B_B + 16);
            }
#pragma unroll
            for (int mi = 0; mi < 4; mi++)
#pragma unroll
                for (int ni = 0; ni < 2; ni++) {
                    MMA_S8(acc1[mi][ni],  a1f[mi], b1f[ni]);
                    MMA_S8(acc23[mi][ni], a1f[mi], b2f[ni]);
                    MMA_S8(acc23[mi][ni], a2f[mi], b1f[ni]);
                    MMA_S8(acc4[mi][ni],  a2f[mi], b2f[ni]);
                }
        }
        __syncthreads();
    }

    // epilogue: C = sa[m]*sb[n]*(acc1 + acc23/256 + acc4/65536) + bias[n]
#pragma unroll
    for (int mi = 0; mi < 4; mi++)
#pragma unroll
        for (int ni = 0; ni < 2; ni++) {
            const int m0r = bm + wm * 64 + mi * 16 + g;
            const int n0 = bn + wn * 16 + ni * 8 + tg * 2;
            const float sb0 = sbv[n0], sb1 = sbv[n0 + 1];
            const float bz0 = bias[n0], bz1 = bias[n0 + 1];
            const float sm0 = sa[m0r], sm1 = sa[m0r + 8];
#pragma unroll
            for (int half = 0; half < 2; half++) {
                const int m = half ? m0r + 8 : m0r;
                const float sm = half ? sm1 : sm0;
                const int i0 = half * 2, i1 = half * 2 + 1;
                float v0 = (float)acc1[mi][ni][i0];
                v0 = fmaf((float)acc23[mi][ni][i0], 0.00390625f, v0);
                v0 = fmaf((float)acc4[mi][ni][i0], 1.52587890625e-05f, v0);
                float v1 = (float)acc1[mi][ni][i1];
                v1 = fmaf((float)acc23[mi][ni][i1], 0.00390625f, v1);
                v1 = fmaf((float)acc4[mi][ni][i1], 1.52587890625e-05f, v1);
                C[(size_t)m * N + n0]     = sm * sb0 * v0 + bz0;
                C[(size_t)m * N + n0 + 1] = sm * sb1 * v1 + bz1;
            }
        }
}

// ---------------------------------------------------------------------------
// Fused fp32 RMSNorm + 3-axis RoPE + scale + bf16 hi/lo split.
// ---------------------------------------------------------------------------
__global__ __launch_bounds__(256)
void norm_rope_split(const float* __restrict__ buf, const float* __restrict__ g,
                     const float* __restrict__ freqs,
                     const int* __restrict__ grid_sizes,
                     __nv_bfloat16* __restrict__ oh, __nv_bfloat16* __restrict__ ol,
                     float scale) {
    __shared__ float red[256];
    __shared__ float s_rn;
    const int row = blockIdx.x;
    const int tid = threadIdx.x;
    const float* rp = buf + (size_t)row * DIM;

    float ss = 0.f;
    for (int i = tid; i < DIM; i += 256) { float v = rp[i]; ss += v * v; }
    red[tid] = ss;
    __syncthreads();
#pragma unroll
    for (int st = 128; st > 0; st >>= 1) {
        if (tid < st) red[tid] += red[tid + st];
        __syncthreads();
    }
    if (tid == 0) s_rn = rsqrtf(red[0] / (float)DIM + 1e-6f);
    __syncthreads();
    const float rn = s_rn;

    const int gh = grid_sizes[1];
    const int gw = grid_sizes[2];
    const int fi = row / (gh * gw);
    const int hi = (row % (gh * gw)) / gw;
    const int wi = row % gw;

    for (int p = tid; p < DIM / 2; p += 256) {
        const int c = p & 63;
        const int pos = (c < 22) ? fi : ((c < 43) ? hi : wi);
        const float theta = freqs[pos * 64 + c];
        float sn, cs;
        sincosf(theta, &sn, &cs);
        const int idx = (p >> 6) * HDIM + 2 * c;
        const float xr = rp[idx]     * rn * g[idx];
        const float xi = rp[idx + 1] * rn * g[idx + 1];
        const float y0 = (xr * cs - xi * sn) * scale;
        const float y1 = (xr * sn + xi * cs) * scale;
        uint2 p2 = split2(y0, y1);
        *(uint32_t*)(oh + (size_t)row * DIM + idx) = p2.x;
        *(uint32_t*)(ol + (size_t)row * DIM + idx) = p2.y;
    }
}

// ---------------------------------------------------------------------------
// fp32 -> bf16 hi/lo split (for V).
// ---------------------------------------------------------------------------
__global__ __launch_bounds__(256)
void split_f32(const float* __restrict__ in, __nv_bfloat16* __restrict__ hi,
               __nv_bfloat16* __restrict__ lo, int n) {
    int i = (blockIdx.x * 256 + threadIdx.x) * 4;
    if (i + 3 >= n) return;
    float4 v = *(const float4*)(in + i);
    uint2 p0 = split2(v.x, v.y);
    uint2 p1 = split2(v.z, v.w);
    *(uint2*)(hi + i) = make_uint2(p0.x, p1.x);
    *(uint2*)(lo + i) = make_uint2(p0.y, p1.y);
}

// ---------------------------------------------------------------------------
// Tensor-core flash attention, bf16x3 (round-5 version; fp32 output).
// ---------------------------------------------------------------------------
#define QSTR 68
#define VSTR 35

__global__ __launch_bounds__(128, 2)
void flash_mma(const __nv_bfloat16* __restrict__ Qh, const __nv_bfloat16* __restrict__ Ql,
               const __nv_bfloat16* __restrict__ Kh, const __nv_bfloat16* __restrict__ Kl,
               const __nv_bfloat16* __restrict__ Vh, const __nv_bfloat16* __restrict__ Vl,
               const int* __restrict__ seq_lens, float* __restrict__ O) {
    extern __shared__ uint32_t sm[];
    uint32_t* sQh = sm;
    uint32_t* sQl = sQh + 64 * QSTR;
    uint32_t* sKh = sQl + 64 * QSTR;
    uint32_t* sKl = sKh + 64 * QSTR;
    uint32_t* sVh = sKl + 64 * QSTR;
    uint32_t* sVl = sVh + 128 * VSTR;

    const int head = blockIdx.y;
    const int q0 = blockIdx.x * 64;
    const int tid = threadIdx.x;
    const int w = tid >> 5, lane = tid & 31;
    const int g = lane >> 2, tg = lane & 3;
    const int m0 = w * 16;
    const int seqlen = seq_lens[0];
    const int GROW = DIM / 2;

    {
        const uint32_t* gQh = (const uint32_t*)(Qh + (size_t)q0 * DIM + head * HDIM);
        const uint32_t* gQl = (const uint32_t*)(Ql + (size_t)q0 * DIM + head * HDIM);
        for (int i = tid; i < 64 * 64; i += 128) {
            const int r = i >> 6, c = i & 63;
            sQh[r * QSTR + c] = gQh[(size_t)r * GROW + c];
            sQl[r * QSTR + c] = gQl[(size_t)r * GROW + c];
        }
    }

    float m[2] = {-1e30f, -1e30f}, l[2] = {0.f, 0.f};
    float o[16][4];
#pragma unroll
    for (int n = 0; n < 16; n++)
#pragma unroll
        for (int r = 0; r < 4; r++) o[n][r] = 0.f;

    for (int k0 = 0; k0 < SEQ; k0 += 64) {
        if (k0 >= seqlen) break;
        __syncthreads();
        {
            const uint32_t* gKh = (const uint32_t*)(Kh + (size_t)k0 * DIM + head * HDIM);
            const uint32_t* gKl = (const uint32_t*)(Kl + (size_t)k0 * DIM + head * HDIM);
            for (int i = tid; i < 64 * 64; i += 128) {
                const int r = i >> 6, c = i & 63;
                sKh[r * QSTR + c] = gKh[(size_t)r * GROW + c];
                sKl[r * QSTR + c] = gKl[(size_t)r * GROW + c];
            }
        }
        {
            const uint32_t* gVh = (const uint32_t*)(Vh + (size_t)k0 * DIM + head * HDIM);
            const uint32_t* gVl = (const uint32_t*)(Vl + (size_t)k0 * DIM + head * HDIM);
            __nv_bfloat16* tVh = (__nv_bfloat16*)sVh;
            __nv_bfloat16* tVl = (__nv_bfloat16*)sVl;
            for (int i = tid; i < 64 * 64; i += 128) {
                const int r = i >> 6, du = i & 63;
                uint32_t vh = gVh[(size_t)r * GROW + du];
                uint32_t vl = gVl[(size_t)r * GROW + du];
                __nv_bfloat162 vh2 = *reinterpret_cast<__nv_bfloat162*>(&vh);
                __nv_bfloat162 vl2 = *reinterpret_cast<__nv_bfloat162*>(&vl);
                tVh[(2 * du)     * (2 * VSTR) + r] = vh2.x;
                tVh[(2 * du + 1) * (2 * VSTR) + r] = vh2.y;
                tVl[(2 * du)     * (2 * VSTR) + r] = vl2.x;
                tVl[(2 * du + 1) * (2 * VSTR) + r] = vl2.y;
            }
        }
        __syncthreads();

        float s[8][4];
#pragma unroll
        for (int j = 0; j < 8; j++)
#pragma unroll
            for (int r = 0; r < 4; r++) s[j][r] = 0.f;

#pragma unroll
        for (int ks = 0; ks < 8; ks++) {
            uint32_t ah[4], al[4];
            const int ab = (m0 + g) * QSTR + ks * 8 + tg;
            ah[0] = sQh[ab];            ah[1] = sQh[ab + 8 * QSTR];
            ah[2] = sQh[ab + 4];        ah[3] = sQh[ab + 8 * QSTR + 4];
            al[0] = sQl[ab];            al[1] = sQl[ab + 8 * QSTR];
            al[2] = sQl[ab + 4];        al[3] = sQl[ab + 8 * QSTR + 4];
#pragma unroll
            for (int j = 0; j < 8; j++) {
                uint32_t bh[2], bl[2];
                const int kb = (8 * j + g) * QSTR + ks * 8 + tg;
                bh[0] = sKh[kb]; bh[1] = sKh[kb + 4];
                bl[0] = sKl[kb]; bl[1] = sKl[kb + 4];
                MMA_BF16(s[j], ah, bh);
                MMA_BF16(s[j], ah, bl);
                MMA_BF16(s[j], al, bh);
            }
        }

        const int kv = seqlen - k0;
        float mx0 = -1e30f, mx1 = -1e30f;
#pragma unroll
        for (int j = 0; j < 8; j++) {
            const int c0 = 8 * j + 2 * tg, c1 = c0 + 1;
            if (c0 >= kv) { s[j][0] = -1e30f; s[j][2] = -1e30f; }
            if (c1 >= kv) { s[j][1] = -1e30f; s[j][3] = -1e30f; }
            mx0 = fmaxf(mx0, fmaxf(s[j][0], s[j][1]));
            mx1 = fmaxf(mx1, fmaxf(s[j][2], s[j][3]));
        }
        mx0 = fmaxf(mx0, __shfl_xor_sync(0xffffffff, mx0, 1));
        mx0 = fmaxf(mx0, __shfl_xor_sync(0xffffffff, mx0, 2));
        mx1 = fmaxf(mx1, __shfl_xor_sync(0xffffffff, mx1, 1));
        mx1 = fmaxf(mx1, __shfl_xor_sync(0xffffffff, mx1, 2));
        const float mn0 = fmaxf(m[0], mx0);
        const float mn1 = fmaxf(m[1], mx1);
        const float a0 = __expf(m[0] - mn0);
        const float a1 = __expf(m[1] - mn1);
        m[0] = mn0; m[1] = mn1;

        float sum0 = 0.f, sum1 = 0.f;
#pragma unroll
        for (int j = 0; j < 8; j++) {
            s[j][0] = __expf(s[j][0] - mn0);
            s[j][1] = __expf(s[j][1] - mn0);
            s[j][2] = __expf(s[j][2] - mn1);
            s[j][3] = __expf(s[j][3] - mn1);
            sum0 += s[j][0] + s[j][1];
            sum1 += s[j][2] + s[j][3];
        }
        sum0 += __shfl_xor_sync(0xffffffff, sum0, 1);
        sum0 += __shfl_xor_sync(0xffffffff, sum0, 2);
        sum1 += __shfl_xor_sync(0xffffffff, sum1, 1);
        sum1 += __shfl_xor_sync(0xffffffff, sum1, 2);
        l[0] = l[0] * a0 + sum0;
        l[1] = l[1] * a1 + sum1;

#pragma unroll
        for (int n = 0; n < 16; n++) {
            o[n][0] *= a0; o[n][1] *= a0;
            o[n][2] *= a1; o[n][3] *= a1;
        }

#pragma unroll
        for (int kp = 0; kp < 4; kp++) {
            uint32_t ph[4], pl[4];
            const int j0 = 2 * kp, j1 = 2 * kp + 1;
            uint2 t;
            t = split2(s[j0][0], s[j0][1]); ph[0] = t.x; pl[0] = t.y;
            t = split2(s[j0][2], s[j0][3]); ph[1] = t.x; pl[1] = t.y;
            t = split2(s[j1][0], s[j1][1]); ph[2] = t.x; pl[2] = t.y;
            t = split2(s[j1][2], s[j1][3]); ph[3] = t.x; pl[3] = t.y;
#pragma unroll
            for (int n = 0; n < 16; n++) {
                uint32_t bh[2], bl[2];
                const int vb = (8 * n + g) * VSTR + kp * 8 + tg;
                bh[0] = sVh[vb]; bh[1] = sVh[vb + 4];
                bl[0] = sVl[vb]; bl[1] = sVl[vb + 4];
                MMA_BF16(o[n], ph, bh);
                MMA_BF16(o[n], ph, bl);
                MMA_BF16(o[n], pl, bh);
            }
        }
    }

    // epilogue: normalize, write fp32
    const float inv0 = 1.f / l[0];
    const float inv1 = 1.f / l[1];
    const int r0 = q0 + m0 + g;
    const int r1 = r0 + 8;
#pragma unroll
    for (int n = 0; n < 16; n++) {
        const int col = head * HDIM + 8 * n + 2 * tg;
        float2* d0 = (float2*)(O + (size_t)r0 * DIM + col);
        float2* d1 = (float2*)(O + (size_t)r1 * DIM + col);
        *d0 = make_float2(o[n][0] * inv0, o[n][1] * inv0);
        *d1 = make_float2(o[n][2] * inv1, o[n][3] * inv1);
    }
}

// ---------------------------------------------------------------------------
// Launch
// ---------------------------------------------------------------------------
extern "C" void kernel_launch(void* const* d_in, const int* in_sizes, int n_in,
                              void* d_out, int out_size) {
    const float* x         = (const float*)d_in[0];
    const int*   seq_lens  = (const int*)  d_in[1];
    const int*   grid_sz   = (const int*)  d_in[2];
    const float* freqs     = (const float*)d_in[3];
    const float* wq        = (const float*)d_in[4];
    const float* bq        = (const float*)d_in[5];
    const float* wk        = (const float*)d_in[6];
    const float* bk        = (const float*)d_in[7];
    const float* wv        = (const float*)d_in[8];
    const float* bv        = (const float*)d_in[9];
    const float* wo        = (const float*)d_in[10];
    const float* bo        = (const float*)d_in[11];
    const float* gq        = (const float*)d_in[12];
    const float* gk        = (const float*)d_in[13];
    float* out = (float*)d_out;

    float *q, *k, *v, *attn;
    cudaGetSymbolAddress((void**)&q,    g_q);
    cudaGetSymbolAddress((void**)&k,    g_k);
    cudaGetSymbolAddress((void**)&v,    g_v);
    cudaGetSymbolAddress((void**)&attn, g_attn);

    int8_t *x1, *x2, *a1, *a2;
    int8_t *wq1, *wq2, *wk1, *wk2, *wv1, *wv2, *wo1, *wo2;
    float *sx, *sa2, *swq, *swk, *swv, *swo;
    cudaGetSymbolAddress((void**)&x1,  g_x1);  cudaGetSymbolAddress((void**)&x2,  g_x2);
    cudaGetSymbolAddress((void**)&a1,  g_a1);  cudaGetSymbolAddress((void**)&a2,  g_a2);
    cudaGetSymbolAddress((void**)&wq1, g_wq1); cudaGetSymbolAddress((void**)&wq2, g_wq2);
    cudaGetSymbolAddress((void**)&wk1, g_wk1); cudaGetSymbolAddress((void**)&wk2, g_wk2);
    cudaGetSymbolAddress((void**)&wv1, g_wv1); cudaGetSymbolAddress((void**)&wv2, g_wv2);
    cudaGetSymbolAddress((void**)&wo1, g_wo1); cudaGetSymbolAddress((void**)&wo2, g_wo2);
    cudaGetSymbolAddress((void**)&sx,  g_sx);  cudaGetSymbolAddress((void**)&sa2, g_sa);
    cudaGetSymbolAddress((void**)&swq, g_swq); cudaGetSymbolAddress((void**)&swk, g_swk);
    cudaGetSymbolAddress((void**)&swv, g_swv); cudaGetSymbolAddress((void**)&swo, g_swo);

    __nv_bfloat16 *qh, *ql, *kh, *kl, *vh, *vl;
    cudaGetSymbolAddress((void**)&qh, g_qh); cudaGetSymbolAddress((void**)&ql, g_ql);
    cudaGetSymbolAddress((void**)&kh, g_kh); cudaGetSymbolAddress((void**)&kl, g_kl);
    cudaGetSymbolAddress((void**)&vh, g_vh); cudaGetSymbolAddress((void**)&vl, g_vl);

    // quantize inputs + weights (dual-limb int8, per-row scales)
    quant8<<<SEQ, 256>>>(x,  x1,  x2,  sx,  DIM);
    quant8<<<DIM, 256>>>(wq, wq1, wq2, swq, DIM);
    quant8<<<DIM, 256>>>(wk, wk1, wk2, swk, DIM);
    quant8<<<DIM, 256>>>(wv, wv1, wv2, swv, DIM);
    quant8<<<DIM, 256>>>(wo, wo1, wo2, swo, DIM);

    const int gemm_smem = 2 * SSTAGE;   // 61440 bytes
    cudaFuncSetAttribute(gemm_s8,
                         cudaFuncAttributeMaxDynamicSharedMemorySize, gemm_smem);

    GemmS8Batch qkv;
    qkv.B1[0] = wq1; qkv.B2[0] = wq2; qkv.sb[0] = swq; qkv.bias[0] = bq; qkv.C[0] = q;
    qkv.B1[1] = wk1; qkv.B2[1] = wk2; qkv.sb[1] = swk; qkv.bias[1] = bk; qkv.C[1] = k;
    qkv.B1[2] = wv1; qkv.B2[2] = wv2; qkv.sb[2] = swv; qkv.bias[2] = bv; qkv.C[2] = v;
    gemm_s8<<<dim3(DIM / 64, SEQ / 128, 3), 256, gemm_smem>>>(
        x1, x2, sx, qkv, SEQ, DIM, DIM);

    const float scale = 0.08838834764831845f;   // 1/sqrt(128)
    norm_rope_split<<<SEQ, 256>>>(q, gq, freqs, grid_sz, qh, ql, scale);
    norm_rope_split<<<SEQ, 256>>>(k, gk, freqs, grid_sz, kh, kl, 1.0f);
    split_f32<<<(SEQ * DIM) / 1024, 256>>>(v, vh, vl, SEQ * DIM);

    const size_t fl_smem = (size_t)(4 * 64 * QSTR + 2 * 128 * VSTR) * sizeof(uint32_t);
    cudaFuncSetAttribute(flash_mma, cudaFuncAttributeMaxDynamicSharedMemorySize, (int)fl_smem);
    flash_mma<<<dim3(SEQ / 64, NHEADS), 128, fl_smem>>>(qh, ql, kh, kl, vh, vl,
                                                        seq_lens, attn);

    quant8<<<SEQ, 256>>>(attn, a1, a2, sa2, DIM);

    GemmS8Batch ob;
    ob.B1[0] = wo1; ob.B2[0] = wo2; ob.sb[0] = swo; ob.bias[0] = bo; ob.C[0] = out;
    ob.B1[1] = wo1; ob.B2[1] = wo2; ob.sb[1] = swo; ob.bias[1] = bo; ob.C[1] = out;
    ob.B1[2] = wo1; ob.B2[2] = wo2; ob.sb[2] = swo; ob.bias[2] = bo; ob.C[2] = out;
    gemm_s8<<<dim3(DIM / 64, SEQ / 128, 1), 256, gemm_smem>>>(
        a1, a2, sa2, ob, SEQ, DIM, DIM);
}

// round 9
// speedup vs baseline: 2.2606x; 2.2606x over previous
#include <cuda_runtime.h>
#include <cuda_bf16.h>
#include <math.h>
#include <stdint.h>

#define DIM    3072
#define NHEADS 24
#define HDIM   128
#define SEQ    2304

// ---------------------------------------------------------------------------
// Scratch (allocation-free: __device__ globals)
// ---------------------------------------------------------------------------
__device__ float g_q[SEQ * DIM];
__device__ float g_k[SEQ * DIM];
__device__ float g_v[SEQ * DIM];

__device__ __nv_bfloat16 g_xh[SEQ * DIM],  g_xl[SEQ * DIM];
__device__ __nv_bfloat16 g_ah[SEQ * DIM],  g_al[SEQ * DIM];
__device__ __nv_bfloat16 g_qh[SEQ * DIM],  g_ql[SEQ * DIM];
__device__ __nv_bfloat16 g_kh[SEQ * DIM],  g_kl[SEQ * DIM];
__device__ __nv_bfloat16 g_vh[SEQ * DIM],  g_vl[SEQ * DIM];
__device__ __nv_bfloat16 g_wqh[DIM * DIM], g_wql[DIM * DIM];
__device__ __nv_bfloat16 g_wkh[DIM * DIM], g_wkl[DIM * DIM];
__device__ __nv_bfloat16 g_wvh[DIM * DIM], g_wvl[DIM * DIM];
__device__ __nv_bfloat16 g_woh[DIM * DIM], g_wol[DIM * DIM];

// fp32 pair -> packed bf16 hi / bf16 lo
__device__ __forceinline__ uint2 split2(float a, float b) {
    __nv_bfloat162 h = __floats2bfloat162_rn(a, b);
    __nv_bfloat162 l = __floats2bfloat162_rn(a - __bfloat162float(h.x),
                                             b - __bfloat162float(h.y));
    uint2 r;
    r.x = *reinterpret_cast<uint32_t*>(&h);
    r.y = *reinterpret_cast<uint32_t*>(&l);
    return r;
}

__device__ __forceinline__ void cp16(uint32_t saddr, const void* gptr) {
    asm volatile("cp.async.cg.shared.global [%0], [%1], 16;"
                 :: "r"(saddr), "l"(gptr));
}

// ---------------------------------------------------------------------------
// fp32 -> (bf16 hi, bf16 lo) split.
// ---------------------------------------------------------------------------
__global__ __launch_bounds__(256)
void split_f32(const float* __restrict__ in, __nv_bfloat16* __restrict__ hi,
               __nv_bfloat16* __restrict__ lo, int n) {
    int i = (blockIdx.x * 256 + threadIdx.x) * 4;
    if (i + 3 >= n) return;
    float4 v = *(const float4*)(in + i);
    uint2 p0 = split2(v.x, v.y);
    uint2 p1 = split2(v.z, v.w);
    *(uint2*)(hi + i) = make_uint2(p0.x, p1.x);
    *(uint2*)(lo + i) = make_uint2(p0.y, p1.y);
}

// ---------------------------------------------------------------------------
// bf16x3 GEMM (NT), cp.async 2-stage pipeline, batched over z.
// BM=BN=128, BK=32, 256 threads = 8 warps (2M x 4N), warp tile 64x32.
// __launch_bounds__(256, 2): force 2 CTAs/SM (reg cap 128).
// ---------------------------------------------------------------------------
#define SSTR 20                       // u32 per smem row (16 data + 4 pad)
#define STG_U32 (4 * 128 * SSTR)      // u32 per stage (4 arrays)
#define ARR_U32 (128 * SSTR)

#define MMA_BF16(d, a, b)                                                     \
    asm volatile("mma.sync.aligned.m16n8k16.row.col.f32.bf16.bf16.f32 "       \
                 "{%0,%1,%2,%3}, {%4,%5,%6,%7}, {%8,%9}, {%0,%1,%2,%3};"      \
                 : "+f"(d[0]), "+f"(d[1]), "+f"(d[2]), "+f"(d[3])             \
                 : "r"(a[0]), "r"(a[1]), "r"(a[2]), "r"(a[3]),                \
                   "r"(b[0]), "r"(b[1]))

struct GemmBatch {
    const __nv_bfloat16* Bh[3];
    const __nv_bfloat16* Bl[3];
    const float*         bias[3];
    float*               C[3];
};

__global__ __launch_bounds__(256, 2)
void gemm_bf16x3_pipe(const __nv_bfloat16* __restrict__ Ah,
                      const __nv_bfloat16* __restrict__ Al,
                      GemmBatch batch, int M, int N, int K) {
    extern __shared__ uint32_t smem[];
    const uint32_t sbase = (uint32_t)__cvta_generic_to_shared(smem);

    const __nv_bfloat16* __restrict__ Bh = batch.Bh[blockIdx.z];
    const __nv_bfloat16* __restrict__ Bl = batch.Bl[blockIdx.z];
    const float* __restrict__ bias = batch.bias[blockIdx.z];
    float* __restrict__ C = batch.C[blockIdx.z];

    const int bm = blockIdx.y * 128, bn = blockIdx.x * 128;
    const int tid = threadIdx.x;
    const int w = tid >> 5, lane = tid & 31;
    const int wm = w & 1, wn = w >> 1;
    const int g = lane >> 2, tg = lane & 3;

    const int r0 = tid >> 2,          q0 = tid & 3;
    const int r1 = (tid + 256) >> 2,  q1 = (tid + 256) & 3;

    float acc[4][4][4];
#pragma unroll
    for (int mi = 0; mi < 4; mi++)
#pragma unroll
        for (int ni = 0; ni < 4; ni++)
#pragma unroll
            for (int r = 0; r < 4; r++) acc[mi][ni][r] = 0.f;

    auto issue = [&](int kt, int stage) {
        const uint32_t sb = sbase + (uint32_t)stage * STG_U32 * 4;
        const uint32_t oA0 = (r0 * SSTR + q0 * 4) * 4;
        const uint32_t oA1 = (r1 * SSTR + q1 * 4) * 4;
        const size_t ga0 = (size_t)(bm + r0) * K + kt + q0 * 8;
        const size_t ga1 = (size_t)(bm + r1) * K + kt + q1 * 8;
        const size_t gb0 = (size_t)(bn + r0) * K + kt + q0 * 8;
        const size_t gb1 = (size_t)(bn + r1) * K + kt + q1 * 8;
        cp16(sb + oA0,                  Ah + ga0);
        cp16(sb + oA1,                  Ah + ga1);
        cp16(sb + ARR_U32 * 4 + oA0,    Al + ga0);
        cp16(sb + ARR_U32 * 4 + oA1,    Al + ga1);
        cp16(sb + ARR_U32 * 8 + oA0,    Bh + gb0);
        cp16(sb + ARR_U32 * 8 + oA1,    Bh + gb1);
        cp16(sb + ARR_U32 * 12 + oA0,   Bl + gb0);
        cp16(sb + ARR_U32 * 12 + oA1,   Bl + gb1);
    };

    const int ntiles = K / 32;
    issue(0, 0);
    asm volatile("cp.async.commit_group;");

    for (int t = 0; t < ntiles; t++) {
        if (t + 1 < ntiles) issue((t + 1) * 32, (t + 1) & 1);
        asm volatile("cp.async.commit_group;");
        asm volatile("cp.async.wait_group 1;");
        __syncthreads();

        const uint32_t* sAh = smem + (t & 1) * STG_U32;
        const uint32_t* sAl = sAh + ARR_U32;
        const uint32_t* sBh = sAl + ARR_U32;
        const uint32_t* sBl = sBh + ARR_U32;

#pragma unroll
        for (int ks = 0; ks < 2; ks++) {
            const int kb = ks * 8;
            uint32_t ah[4][4], al[4][4], bh[4][2], bl[4][2];
#pragma unroll
            for (int mi = 0; mi < 4; mi++) {
                const int r = wm * 64 + mi * 16 + g;
                ah[mi][0] = sAh[r * SSTR + kb + tg];
                ah[mi][1] = sAh[(r + 8) * SSTR + kb + tg];
                ah[mi][2] = sAh[r * SSTR + kb + tg + 4];
                ah[mi][3] = sAh[(r + 8) * SSTR + kb + tg + 4];
                al[mi][0] = sAl[r * SSTR + kb + tg];
                al[mi][1] = sAl[(r + 8) * SSTR + kb + tg];
                al[mi][2] = sAl[r * SSTR + kb + tg + 4];
                al[mi][3] = sAl[(r + 8) * SSTR + kb + tg + 4];
            }
#pragma unroll
            for (int ni = 0; ni < 4; ni++) {
                const int c = wn * 32 + ni * 8 + g;
                bh[ni][0] = sBh[c * SSTR + kb + tg];
                bh[ni][1] = sBh[c * SSTR + kb + tg + 4];
                bl[ni][0] = sBl[c * SSTR + kb + tg];
                bl[ni][1] = sBl[c * SSTR + kb + tg + 4];
            }
#pragma unroll
            for (int mi = 0; mi < 4; mi++)
#pragma unroll
                for (int ni = 0; ni < 4; ni++) {
                    MMA_BF16(acc[mi][ni], ah[mi], bh[ni]);
                    MMA_BF16(acc[mi][ni], ah[mi], bl[ni]);
                    MMA_BF16(acc[mi][ni], al[mi], bh[ni]);
                }
        }
        __syncthreads();
    }

#pragma unroll
    for (int mi = 0; mi < 4; mi++)
#pragma unroll
        for (int ni = 0; ni < 4; ni++) {
            const int r = bm + wm * 64 + mi * 16 + g;
            const int c = bn + wn * 32 + ni * 8 + tg * 2;
            const float b0 = bias[c], b1 = bias[c + 1];
            C[(size_t)r * N + c]           = acc[mi][ni][0] + b0;
            C[(size_t)r * N + c + 1]       = acc[mi][ni][1] + b1;
            C[(size_t)(r + 8) * N + c]     = acc[mi][ni][2] + b0;
            C[(size_t)(r + 8) * N + c + 1] = acc[mi][ni][3] + b1;
        }
}

// ---------------------------------------------------------------------------
// Fused fp32 RMSNorm + 3-axis RoPE + scale + bf16 hi/lo split.
// ---------------------------------------------------------------------------
__global__ __launch_bounds__(256)
void norm_rope_split(const float* __restrict__ buf, const float* __restrict__ g,
                     const float* __restrict__ freqs,
                     const int* __restrict__ grid_sizes,
                     __nv_bfloat16* __restrict__ oh, __nv_bfloat16* __restrict__ ol,
                     float scale) {
    __shared__ float red[256];
    __shared__ float s_rn;
    const int row = blockIdx.x;
    const int tid = threadIdx.x;
    const float* rp = buf + (size_t)row * DIM;

    float ss = 0.f;
    for (int i = tid; i < DIM; i += 256) { float v = rp[i]; ss += v * v; }
    red[tid] = ss;
    __syncthreads();
#pragma unroll
    for (int st = 128; st > 0; st >>= 1) {
        if (tid < st) red[tid] += red[tid + st];
        __syncthreads();
    }
    if (tid == 0) s_rn = rsqrtf(red[0] / (float)DIM + 1e-6f);
    __syncthreads();
    const float rn = s_rn;

    const int gh = grid_sizes[1];
    const int gw = grid_sizes[2];
    const int fi = row / (gh * gw);
    const int hi = (row % (gh * gw)) / gw;
    const int wi = row % gw;

    for (int p = tid; p < DIM / 2; p += 256) {
        const int c = p & 63;
        const int pos = (c < 22) ? fi : ((c < 43) ? hi : wi);
        const float theta = freqs[pos * 64 + c];
        float sn, cs;
        sincosf(theta, &sn, &cs);
        const int idx = (p >> 6) * HDIM + 2 * c;
        const float xr = rp[idx]     * rn * g[idx];
        const float xi = rp[idx + 1] * rn * g[idx + 1];
        const float y0 = (xr * cs - xi * sn) * scale;
        const float y1 = (xr * sn + xi * cs) * scale;
        uint2 p2 = split2(y0, y1);
        *(uint32_t*)(oh + (size_t)row * DIM + idx) = p2.x;
        *(uint32_t*)(ol + (size_t)row * DIM + idx) = p2.y;
    }
}

// ---------------------------------------------------------------------------
// Tensor-core flash attention (round-5 version, unchanged — passing).
// ---------------------------------------------------------------------------
#define QSTR 68
#define VSTR 35

__global__ __launch_bounds__(128, 2)
void flash_mma(const __nv_bfloat16* __restrict__ Qh, const __nv_bfloat16* __restrict__ Ql,
               const __nv_bfloat16* __restrict__ Kh, const __nv_bfloat16* __restrict__ Kl,
               const __nv_bfloat16* __restrict__ Vh, const __nv_bfloat16* __restrict__ Vl,
               const int* __restrict__ seq_lens,
               __nv_bfloat16* __restrict__ Oh, __nv_bfloat16* __restrict__ Ol) {
    extern __shared__ uint32_t sm[];
    uint32_t* sQh = sm;
    uint32_t* sQl = sQh + 64 * QSTR;
    uint32_t* sKh = sQl + 64 * QSTR;
    uint32_t* sKl = sKh + 64 * QSTR;
    uint32_t* sVh = sKl + 64 * QSTR;
    uint32_t* sVl = sVh + 128 * VSTR;

    const int head = blockIdx.y;
    const int q0 = blockIdx.x * 64;
    const int tid = threadIdx.x;
    const int w = tid >> 5, lane = tid & 31;
    const int g = lane >> 2, tg = lane & 3;
    const int m0 = w * 16;
    const int seqlen = seq_lens[0];
    const int GROW = DIM / 2;

    {
        const uint32_t* gQh = (const uint32_t*)(Qh + (size_t)q0 * DIM + head * HDIM);
        const uint32_t* gQl = (const uint32_t*)(Ql + (size_t)q0 * DIM + head * HDIM);
        for (int i = tid; i < 64 * 64; i += 128) {
            const int r = i >> 6, c = i & 63;
            sQh[r * QSTR + c] = gQh[(size_t)r * GROW + c];
            sQl[r * QSTR + c] = gQl[(size_t)r * GROW + c];
        }
    }

    float m[2] = {-1e30f, -1e30f}, l[2] = {0.f, 0.f};
    float o[16][4];
#pragma unroll
    for (int n = 0; n < 16; n++)
#pragma unroll
        for (int r = 0; r < 4; r++) o[n][r] = 0.f;

    for (int k0 = 0; k0 < SEQ; k0 += 64) {
        if (k0 >= seqlen) break;
        __syncthreads();
        {
            const uint32_t* gKh = (const uint32_t*)(Kh + (size_t)k0 * DIM + head * HDIM);
            const uint32_t* gKl = (const uint32_t*)(Kl + (size_t)k0 * DIM + head * HDIM);
            for (int i = tid; i < 64 * 64; i += 128) {
                const int r = i >> 6, c = i & 63;
                sKh[r * QSTR + c] = gKh[(size_t)r * GROW + c];
                sKl[r * QSTR + c] = gKl[(size_t)r * GROW + c];
            }
        }
        {
            const uint32_t* gVh = (const uint32_t*)(Vh + (size_t)k0 * DIM + head * HDIM);
            const uint32_t* gVl = (const uint32_t*)(Vl + (size_t)k0 * DIM + head * HDIM);
            __nv_bfloat16* tVh = (__nv_bfloat16*)sVh;
            __nv_bfloat16* tVl = (__nv_bfloat16*)sVl;
            for (int i = tid; i < 64 * 64; i += 128) {
                const int r = i >> 6, du = i & 63;
                uint32_t vh = gVh[(size_t)r * GROW + du];
                uint32_t vl = gVl[(size_t)r * GROW + du];
                __nv_bfloat162 vh2 = *reinterpret_cast<__nv_bfloat162*>(&vh);
                __nv_bfloat162 vl2 = *reinterpret_cast<__nv_bfloat162*>(&vl);
                tVh[(2 * du)     * (2 * VSTR) + r] = vh2.x;
                tVh[(2 * du + 1) * (2 * VSTR) + r] = vh2.y;
                tVl[(2 * du)     * (2 * VSTR) + r] = vl2.x;
                tVl[(2 * du + 1) * (2 * VSTR) + r] = vl2.y;
            }
        }
        __syncthreads();

        float s[8][4];
#pragma unroll
        for (int j = 0; j < 8; j++)
#pragma unroll
            for (int r = 0; r < 4; r++) s[j][r] = 0.f;

#pragma unroll
        for (int ks = 0; ks < 8; ks++) {
            uint32_t ah[4], al[4];
            const int ab = (m0 + g) * QSTR + ks * 8 + tg;
            ah[0] = sQh[ab];            ah[1] = sQh[ab + 8 * QSTR];
            ah[2] = sQh[ab + 4];        ah[3] = sQh[ab + 8 * QSTR + 4];
            al[0] = sQl[ab];            al[1] = sQl[ab + 8 * QSTR];
            al[2] = sQl[ab + 4];        al[3] = sQl[ab + 8 * QSTR + 4];
#pragma unroll
            for (int j = 0; j < 8; j++) {
                uint32_t bh[2], bl[2];
                const int kb = (8 * j + g) * QSTR + ks * 8 + tg;
                bh[0] = sKh[kb]; bh[1] = sKh[kb + 4];
                bl[0] = sKl[kb]; bl[1] = sKl[kb + 4];
                MMA_BF16(s[j], ah, bh);
                MMA_BF16(s[j], ah, bl);
                MMA_BF16(s[j], al, bh);
            }
        }

        const int kv = seqlen - k0;
        float mx0 = -1e30f, mx1 = -1e30f;
#pragma unroll
        for (int j = 0; j < 8; j++) {
            const int c0 = 8 * j + 2 * tg, c1 = c0 + 1;
            if (c0 >= kv) { s[j][0] = -1e30f; s[j][2] = -1e30f; }
            if (c1 >= kv) { s[j][1] = -1e30f; s[j][3] = -1e30f; }
            mx0 = fmaxf(mx0, fmaxf(s[j][0], s[j][1]));
            mx1 = fmaxf(mx1, fmaxf(s[j][2], s[j][3]));
        }
        mx0 = fmaxf(mx0, __shfl_xor_sync(0xffffffff, mx0, 1));
        mx0 = fmaxf(mx0, __shfl_xor_sync(0xffffffff, mx0, 2));
        mx1 = fmaxf(mx1, __shfl_xor_sync(0xffffffff, mx1, 1));
        mx1 = fmaxf(mx1, __shfl_xor_sync(0xffffffff, mx1, 2));
        const float mn0 = fmaxf(m[0], mx0);
        const float mn1 = fmaxf(m[1], mx1);
        const float a0 = __expf(m[0] - mn0);
        const float a1 = __expf(m[1] - mn1);
        m[0] = mn0; m[1] = mn1;

        float sum0 = 0.f, sum1 = 0.f;
#pragma unroll
        for (int j = 0; j < 8; j++) {
            s[j][0] = __expf(s[j][0] - mn0);
            s[j][1] = __expf(s[j][1] - mn0);
            s[j][2] = __expf(s[j][2] - mn1);
            s[j][3] = __expf(s[j][3] - mn1);
            sum0 += s[j][0] + s[j][1];
            sum1 += s[j][2] + s[j][3];
        }
        sum0 += __shfl_xor_sync(0xffffffff, sum0, 1);
        sum0 += __shfl_xor_sync(0xffffffff, sum0, 2);
        sum1 += __shfl_xor_sync(0xffffffff, sum1, 1);
        sum1 += __shfl_xor_sync(0xffffffff, sum1, 2);
        l[0] = l[0] * a0 + sum0;
        l[1] = l[1] * a1 + sum1;

#pragma unroll
        for (int n = 0; n < 16; n++) {
            o[n][0] *= a0; o[n][1] *= a0;
            o[n][2] *= a1; o[n][3] *= a1;
        }

#pragma unroll
        for (int kp = 0; kp < 4; kp++) {
            uint32_t ph[4], pl[4];
            const int j0 = 2 * kp, j1 = 2 * kp + 1;
            uint2 t;
            t = split2(s[j0][0], s[j0][1]); ph[0] = t.x; pl[0] = t.y;
            t = split2(s[j0][2], s[j0][3]); ph[1] = t.x; pl[1] = t.y;
            t = split2(s[j1][0], s[j1][1]); ph[2] = t.x; pl[2] = t.y;
            t = split2(s[j1][2], s[j1][3]); ph[3] = t.x; pl[3] = t.y;
#pragma unroll
            for (int n = 0; n < 16; n++) {
                uint32_t bh[2], bl[2];
                const int vb = (8 * n + g) * VSTR + kp * 8 + tg;
                bh[0] = sVh[vb]; bh[1] = sVh[vb + 4];
                bl[0] = sVl[vb]; bl[1] = sVl[vb + 4];
                MMA_BF16(o[n], ph, bh);
                MMA_BF16(o[n], ph, bl);
                MMA_BF16(o[n], pl, bh);
            }
        }
    }

    const float inv0 = 1.f / l[0];
    const float inv1 = 1.f / l[1];
    const int r0 = q0 + m0 + g;
    const int r1 = r0 + 8;
    uint32_t* oHh = (uint32_t*)(Oh);
    uint32_t* oLl = (uint32_t*)(Ol);
#pragma unroll
    for (int n = 0; n < 16; n++) {
        const int col = head * HDIM + 8 * n + 2 * tg;
        uint2 p0 = split2(o[n][0] * inv0, o[n][1] * inv0);
        oHh[(size_t)r0 * GROW + col / 2] = p0.x;
        oLl[(size_t)r0 * GROW + col / 2] = p0.y;
        uint2 p1 = split2(o[n][2] * inv1, o[n][3] * inv1);
        oHh[(size_t)r1 * GROW + col / 2] = p1.x;
        oLl[(size_t)r1 * GROW + col / 2] = p1.y;
    }
}

// ---------------------------------------------------------------------------
// Launch  (order chosen so launch #5 = QKV GEMM — that's what ncu profiles)
// ---------------------------------------------------------------------------
extern "C" void kernel_launch(void* const* d_in, const int* in_sizes, int n_in,
                              void* d_out, int out_size) {
    const float* x         = (const float*)d_in[0];
    const int*   seq_lens  = (const int*)  d_in[1];
    const int*   grid_sz   = (const int*)  d_in[2];
    const float* freqs     = (const float*)d_in[3];
    const float* wq        = (const float*)d_in[4];
    const float* bq        = (const float*)d_in[5];
    const float* wk        = (const float*)d_in[6];
    const float* bk        = (const float*)d_in[7];
    const float* wv        = (const float*)d_in[8];
    const float* bv        = (const float*)d_in[9];
    const float* wo        = (const float*)d_in[10];
    const float* bo        = (const float*)d_in[11];
    const float* gq        = (const float*)d_in[12];
    const float* gk        = (const float*)d_in[13];
    float* out = (float*)d_out;

    float *q, *k, *v;
    cudaGetSymbolAddress((void**)&q, g_q);
    cudaGetSymbolAddress((void**)&k, g_k);
    cudaGetSymbolAddress((void**)&v, g_v);

    __nv_bfloat16 *xh, *xl, *ah, *al, *qh, *ql, *kh, *kl, *vh, *vl;
    __nv_bfloat16 *wqh, *wql, *wkh, *wkl, *wvh, *wvl, *woh, *wol;
    cudaGetSymbolAddress((void**)&xh,  g_xh);  cudaGetSymbolAddress((void**)&xl,  g_xl);
    cudaGetSymbolAddress((void**)&ah,  g_ah);  cudaGetSymbolAddress((void**)&al,  g_al);
    cudaGetSymbolAddress((void**)&qh,  g_qh);  cudaGetSymbolAddress((void**)&ql,  g_ql);
    cudaGetSymbolAddress((void**)&kh,  g_kh);  cudaGetSymbolAddress((void**)&kl,  g_kl);
    cudaGetSymbolAddress((void**)&vh,  g_vh);  cudaGetSymbolAddress((void**)&vl,  g_vl);
    cudaGetSymbolAddress((void**)&wqh, g_wqh); cudaGetSymbolAddress((void**)&wql, g_wql);
    cudaGetSymbolAddress((void**)&wkh, g_wkh); cudaGetSymbolAddress((void**)&wkl, g_wkl);
    cudaGetSymbolAddress((void**)&wvh, g_wvh); cudaGetSymbolAddress((void**)&wvl, g_wvl);
    cudaGetSymbolAddress((void**)&woh, g_woh); cudaGetSymbolAddress((void**)&wol, g_wol);

    const int nX = SEQ * DIM, nW = DIM * DIM;
    const int gemm_smem = 2 * STG_U32 * 4;   // 81920 bytes
    cudaFuncSetAttribute(gemm_bf16x3_pipe,
                         cudaFuncAttributeMaxDynamicSharedMemorySize, gemm_smem);

    // launches 1-4: splits needed for the QKV GEMM
    split_f32<<<nX / 1024, 256>>>(x,  xh,  xl,  nX);
    split_f32<<<nW / 1024, 256>>>(wq, wqh, wql, nW);
    split_f32<<<nW / 1024, 256>>>(wk, wkh, wkl, nW);
    split_f32<<<nW / 1024, 256>>>(wv, wvh, wvl, nW);

    // launch 5: fused QKV GEMM (gets profiled by ncu)
    GemmBatch qkv;
    qkv.Bh[0] = wqh; qkv.Bl[0] = wql; qkv.bias[0] = bq; qkv.C[0] = q;
    qkv.Bh[1] = wkh; qkv.Bl[1] = wkl; qkv.bias[1] = bk; qkv.C[1] = k;
    qkv.Bh[2] = wvh; qkv.Bl[2] = wvl; qkv.bias[2] = bv; qkv.C[2] = v;
    gemm_bf16x3_pipe<<<dim3(DIM / 128, SEQ / 128, 3), 256, gemm_smem>>>(
        xh, xl, qkv, SEQ, DIM, DIM);

    // remaining prep
    split_f32<<<nW / 1024, 256>>>(wo, woh, wol, nW);

    const float scale = 0.08838834764831845f;   // 1/sqrt(128)
    norm_rope_split<<<SEQ, 256>>>(q, gq, freqs, grid_sz, qh, ql, scale);
    norm_rope_split<<<SEQ, 256>>>(k, gk, freqs, grid_sz, kh, kl, 1.0f);
    split_f32<<<nX / 1024, 256>>>(v, vh, vl, nX);

    const size_t fl_smem = (size_t)(4 * 64 * QSTR + 2 * 128 * VSTR) * sizeof(uint32_t);
    cudaFuncSetAttribute(flash_mma, cudaFuncAttributeMaxDynamicSharedMemorySize, (int)fl_smem);
    flash_mma<<<dim3(SEQ / 64, NHEADS), 128, fl_smem>>>(qh, ql, kh, kl, vh, vl,
                                                        seq_lens, ah, al);

    GemmBatch ob;
    ob.Bh[0] = woh; ob.Bl[0] = wol; ob.bias[0] = bo; ob.C[0] = out;
    ob.Bh[1] = woh; ob.Bl[1] = wol; ob.bias[1] = bo; ob.C[1] = out;
    ob.Bh[2] = woh; ob.Bl[2] = wol; ob.bias[2] = bo; ob.C[2] = out;
    gemm_bf16x3_pipe<<<dim3(DIM / 128, SEQ / 128, 1), 256, gemm_smem>>>(
        ah, al, ob, SEQ, DIM, DIM);
}

// round 10
// speedup vs baseline: 2.7190x; 1.2028x over previous
#include <cuda_runtime.h>
#include <cuda_bf16.h>
#include <cuda_fp16.h>
#include <math.h>
#include <stdint.h>

#define DIM    3072
#define NHEADS 24
#define HDIM   128
#define SEQ    2304

// ---------------------------------------------------------------------------
// Scratch (allocation-free: __device__ globals)
// ---------------------------------------------------------------------------
__device__ float g_q[SEQ * DIM];
__device__ float g_k[SEQ * DIM];
__device__ float g_v[SEQ * DIM];

__device__ __half g_xh[SEQ * DIM], g_xl[SEQ * DIM];     // x  fp16 hi/lo
__device__ __half g_ah[SEQ * DIM], g_al[SEQ * DIM];     // attn fp16 hi/lo
__device__ __half g_wq[DIM * DIM], g_wk[DIM * DIM];     // weights single fp16
__device__ __half g_wv[DIM * DIM], g_wo[DIM * DIM];

__device__ __nv_bfloat16 g_qh[SEQ * DIM], g_ql[SEQ * DIM];
__device__ __nv_bfloat16 g_kh[SEQ * DIM], g_kl[SEQ * DIM];
__device__ __nv_bfloat16 g_vh[SEQ * DIM], g_vl[SEQ * DIM];

// fp32 pair -> packed bf16 hi / bf16 lo
__device__ __forceinline__ uint2 split2(float a, float b) {
    __nv_bfloat162 h = __floats2bfloat162_rn(a, b);
    __nv_bfloat162 l = __floats2bfloat162_rn(a - __bfloat162float(h.x),
                                             b - __bfloat162float(h.y));
    uint2 r;
    r.x = *reinterpret_cast<uint32_t*>(&h);
    r.y = *reinterpret_cast<uint32_t*>(&l);
    return r;
}

// fp32 pair -> packed fp16 hi / fp16 lo
__device__ __forceinline__ uint2 split2h(float a, float b) {
    __half2 h = __floats2half2_rn(a, b);
    __half2 l = __floats2half2_rn(a - __half2float(__low2half(h)),
                                  b - __half2float(__high2half(h)));
    uint2 r;
    r.x = *reinterpret_cast<uint32_t*>(&h);
    r.y = *reinterpret_cast<uint32_t*>(&l);
    return r;
}

__device__ __forceinline__ void cp16(uint32_t saddr, const void* gptr) {
    asm volatile("cp.async.cg.shared.global [%0], [%1], 16;"
                 :: "r"(saddr), "l"(gptr));
}

#define MMA_BF16(d, a, b)                                                     \
    asm volatile("mma.sync.aligned.m16n8k16.row.col.f32.bf16.bf16.f32 "       \
                 "{%0,%1,%2,%3}, {%4,%5,%6,%7}, {%8,%9}, {%0,%1,%2,%3};"      \
                 : "+f"(d[0]), "+f"(d[1]), "+f"(d[2]), "+f"(d[3])             \
                 : "r"(a[0]), "r"(a[1]), "r"(a[2]), "r"(a[3]),                \
                   "r"(b[0]), "r"(b[1]))

#define MMA_F16(d, a, b)                                                      \
    asm volatile("mma.sync.aligned.m16n8k16.row.col.f32.f16.f16.f32 "         \
                 "{%0,%1,%2,%3}, {%4,%5,%6,%7}, {%8,%9}, {%0,%1,%2,%3};"      \
                 : "+f"(d[0]), "+f"(d[1]), "+f"(d[2]), "+f"(d[3])             \
                 : "r"(a[0]), "r"(a[1]), "r"(a[2]), "r"(a[3]),                \
                   "r"(b[0]), "r"(b[1]))

// ---------------------------------------------------------------------------
// fp32 -> (fp16 hi, fp16 lo) split.
// ---------------------------------------------------------------------------
__global__ __launch_bounds__(256)
void split_f16(const float* __restrict__ in, __half* __restrict__ hi,
               __half* __restrict__ lo, int n) {
    int i = (blockIdx.x * 256 + threadIdx.x) * 4;
    if (i + 3 >= n) return;
    float4 v = *(const float4*)(in + i);
    uint2 p0 = split2h(v.x, v.y);
    uint2 p1 = split2h(v.z, v.w);
    *(uint2*)(hi + i) = make_uint2(p0.x, p1.x);
    *(uint2*)(lo + i) = make_uint2(p0.y, p1.y);
}

// ---------------------------------------------------------------------------
// fp32 -> fp16 (single, round-to-nearest).
// ---------------------------------------------------------------------------
__global__ __launch_bounds__(256)
void round_f16(const float* __restrict__ in, __half* __restrict__ out, int n) {
    int i = (blockIdx.x * 256 + threadIdx.x) * 4;
    if (i + 3 >= n) return;
    float4 v = *(const float4*)(in + i);
    __half2 h0 = __floats2half2_rn(v.x, v.y);
    __half2 h1 = __floats2half2_rn(v.z, v.w);
    *(uint2*)(out + i) = make_uint2(*reinterpret_cast<uint32_t*>(&h0),
                                    *reinterpret_cast<uint32_t*>(&h1));
}

// ---------------------------------------------------------------------------
// fp16x2 GEMM (NT): C = (Ah+Al) . B + bias.  2 MMA passes (AhB + AlB).
// BM=BN=128, BK=32, 256 threads = 8 warps (2M x 4N), cp.async 2-stage.
// ---------------------------------------------------------------------------
#define SSTR 20                       // u32 per smem row (16 data + 4 pad)
#define ARR_U32 (128 * SSTR)
#define STG_U32 (3 * ARR_U32)         // Ah, Al, B
#define ARR_BYTES (ARR_U32 * 4)
#define STG_BYTES (STG_U32 * 4)

struct GemmF16Batch {
    const __half* B[3];
    const float*  bias[3];
    float*        C[3];
};

__global__ __launch_bounds__(256, 2)
void gemm_f16x2_pipe(const __half* __restrict__ Ah,
                     const __half* __restrict__ Al,
                     GemmF16Batch batch, int M, int N, int K) {
    extern __shared__ uint32_t smem[];
    const uint32_t sbase = (uint32_t)__cvta_generic_to_shared(smem);

    const __half* __restrict__ B = batch.B[blockIdx.z];
    const float* __restrict__ bias = batch.bias[blockIdx.z];
    float* __restrict__ C = batch.C[blockIdx.z];

    const int bm = blockIdx.y * 128, bn = blockIdx.x * 128;
    const int tid = threadIdx.x;
    const int w = tid >> 5, lane = tid & 31;
    const int wm = w & 1, wn = w >> 1;
    const int g = lane >> 2, tg = lane & 3;

    float acc[4][4][4];
#pragma unroll
    for (int mi = 0; mi < 4; mi++)
#pragma unroll
        for (int ni = 0; ni < 4; ni++)
#pragma unroll
            for (int r = 0; r < 4; r++) acc[mi][ni][r] = 0.f;

    // loader: 1536 16B chunks/stage (Ah 512, Al 512, B 512), 6 per thread
    auto issue = [&](int kt, int stage) {
        const uint32_t sb = sbase + (uint32_t)stage * STG_BYTES;
#pragma unroll
        for (int i = 0; i < 6; i++) {
            const int c = tid + i * 256;
            const int arr = c >> 9;            // 0..2
            const int cid = c & 511;
            const int r = cid >> 2, q = cid & 3;
            const uint32_t dst = sb + arr * ARR_BYTES + (r * SSTR + q * 4) * 4;
            const __half* src;
            if      (arr == 0) src = Ah + (size_t)(bm + r) * K + kt + q * 8;
            else if (arr == 1) src = Al + (size_t)(bm + r) * K + kt + q * 8;
            else               src = B  + (size_t)(bn + r) * K + kt + q * 8;
            cp16(dst, src);
        }
    };

    const int ntiles = K / 32;
    issue(0, 0);
    asm volatile("cp.async.commit_group;");

    for (int t = 0; t < ntiles; t++) {
        if (t + 1 < ntiles) issue((t + 1) * 32, (t + 1) & 1);
        asm volatile("cp.async.commit_group;");
        asm volatile("cp.async.wait_group 1;");
        __syncthreads();

        const uint32_t* sAh = smem + (t & 1) * STG_U32;
        const uint32_t* sAl = sAh + ARR_U32;
        const uint32_t* sB  = sAl + ARR_U32;

#pragma unroll
        for (int ks = 0; ks < 2; ks++) {
            const int kb = ks * 8;
            uint32_t ah[4][4], al[4][4], bf[4][2];
#pragma unroll
            for (int mi = 0; mi < 4; mi++) {
                const int r = wm * 64 + mi * 16 + g;
                ah[mi][0] = sAh[r * SSTR + kb + tg];
                ah[mi][1] = sAh[(r + 8) * SSTR + kb + tg];
                ah[mi][2] = sAh[r * SSTR + kb + tg + 4];
                ah[mi][3] = sAh[(r + 8) * SSTR + kb + tg + 4];
                al[mi][0] = sAl[r * SSTR + kb + tg];
                al[mi][1] = sAl[(r + 8) * SSTR + kb + tg];
                al[mi][2] = sAl[r * SSTR + kb + tg + 4];
                al[mi][3] = sAl[(r + 8) * SSTR + kb + tg + 4];
            }
#pragma unroll
            for (int ni = 0; ni < 4; ni++) {
                const int c = wn * 32 + ni * 8 + g;
                bf[ni][0] = sB[c * SSTR + kb + tg];
                bf[ni][1] = sB[c * SSTR + kb + tg + 4];
            }
#pragma unroll
            for (int mi = 0; mi < 4; mi++)
#pragma unroll
                for (int ni = 0; ni < 4; ni++) {
                    MMA_F16(acc[mi][ni], ah[mi], bf[ni]);
                    MMA_F16(acc[mi][ni], al[mi], bf[ni]);
                }
        }
        __syncthreads();
    }

#pragma unroll
    for (int mi = 0; mi < 4; mi++)
#pragma unroll
        for (int ni = 0; ni < 4; ni++) {
            const int r = bm + wm * 64 + mi * 16 + g;
            const int c = bn + wn * 32 + ni * 8 + tg * 2;
            const float b0 = bias[c], b1 = bias[c + 1];
            C[(size_t)r * N + c]           = acc[mi][ni][0] + b0;
            C[(size_t)r * N + c + 1]       = acc[mi][ni][1] + b1;
            C[(size_t)(r + 8) * N + c]     = acc[mi][ni][2] + b0;
            C[(size_t)(r + 8) * N + c + 1] = acc[mi][ni][3] + b1;
        }
}

// ---------------------------------------------------------------------------
// Fused fp32 RMSNorm + 3-axis RoPE + scale + bf16 hi/lo split.
// ---------------------------------------------------------------------------
__global__ __launch_bounds__(256)
void norm_rope_split(const float* __restrict__ buf, const float* __restrict__ g,
                     const float* __restrict__ freqs,
                     const int* __restrict__ grid_sizes,
                     __nv_bfloat16* __restrict__ oh, __nv_bfloat16* __restrict__ ol,
                     float scale) {
    __shared__ float red[256];
    __shared__ float s_rn;
    const int row = blockIdx.x;
    const int tid = threadIdx.x;
    const float* rp = buf + (size_t)row * DIM;

    float ss = 0.f;
    for (int i = tid; i < DIM; i += 256) { float v = rp[i]; ss += v * v; }
    red[tid] = ss;
    __syncthreads();
#pragma unroll
    for (int st = 128; st > 0; st >>= 1) {
        if (tid < st) red[tid] += red[tid + st];
        __syncthreads();
    }
    if (tid == 0) s_rn = rsqrtf(red[0] / (float)DIM + 1e-6f);
    __syncthreads();
    const float rn = s_rn;

    const int gh = grid_sizes[1];
    const int gw = grid_sizes[2];
    const int fi = row / (gh * gw);
    const int hi = (row % (gh * gw)) / gw;
    const int wi = row % gw;

    for (int p = tid; p < DIM / 2; p += 256) {
        const int c = p & 63;
        const int pos = (c < 22) ? fi : ((c < 43) ? hi : wi);
        const float theta = freqs[pos * 64 + c];
        float sn, cs;
        sincosf(theta, &sn, &cs);
        const int idx = (p >> 6) * HDIM + 2 * c;
        const float xr = rp[idx]     * rn * g[idx];
        const float xi = rp[idx + 1] * rn * g[idx + 1];
        const float y0 = (xr * cs - xi * sn) * scale;
        const float y1 = (xr * sn + xi * cs) * scale;
        uint2 p2 = split2(y0, y1);
        *(uint32_t*)(oh + (size_t)row * DIM + idx) = p2.x;
        *(uint32_t*)(ol + (size_t)row * DIM + idx) = p2.y;
    }
}

// ---------------------------------------------------------------------------
// fp32 -> bf16 hi/lo split (for V).
// ---------------------------------------------------------------------------
__global__ __launch_bounds__(256)
void split_f32(const float* __restrict__ in, __nv_bfloat16* __restrict__ hi,
               __nv_bfloat16* __restrict__ lo, int n) {
    int i = (blockIdx.x * 256 + threadIdx.x) * 4;
    if (i + 3 >= n) return;
    float4 v = *(const float4*)(in + i);
    uint2 p0 = split2(v.x, v.y);
    uint2 p1 = split2(v.z, v.w);
    *(uint2*)(hi + i) = make_uint2(p0.x, p1.x);
    *(uint2*)(lo + i) = make_uint2(p0.y, p1.y);
}

// ---------------------------------------------------------------------------
// Tensor-core flash attention, bf16x3 (unchanged math); epilogue writes
// fp16 hi/lo for the fp16x2 O-projection.
// ---------------------------------------------------------------------------
#define QSTR 68
#define VSTR 35

__global__ __launch_bounds__(128, 2)
void flash_mma(const __nv_bfloat16* __restrict__ Qh, const __nv_bfloat16* __restrict__ Ql,
               const __nv_bfloat16* __restrict__ Kh, const __nv_bfloat16* __restrict__ Kl,
               const __nv_bfloat16* __restrict__ Vh, const __nv_bfloat16* __restrict__ Vl,
               const int* __restrict__ seq_lens,
               __half* __restrict__ Oh, __half* __restrict__ Ol) {
    extern __shared__ uint32_t sm[];
    uint32_t* sQh = sm;
    uint32_t* sQl = sQh + 64 * QSTR;
    uint32_t* sKh = sQl + 64 * QSTR;
    uint32_t* sKl = sKh + 64 * QSTR;
    uint32_t* sVh = sKl + 64 * QSTR;
    uint32_t* sVl = sVh + 128 * VSTR;

    const int head = blockIdx.y;
    const int q0 = blockIdx.x * 64;
    const int tid = threadIdx.x;
    const int w = tid >> 5, lane = tid & 31;
    const int g = lane >> 2, tg = lane & 3;
    const int m0 = w * 16;
    const int seqlen = seq_lens[0];
    const int GROW = DIM / 2;

    {
        const uint32_t* gQh = (const uint32_t*)(Qh + (size_t)q0 * DIM + head * HDIM);
        const uint32_t* gQl = (const uint32_t*)(Ql + (size_t)q0 * DIM + head * HDIM);
        for (int i = tid; i < 64 * 64; i += 128) {
            const int r = i >> 6, c = i & 63;
            sQh[r * QSTR + c] = gQh[(size_t)r * GROW + c];
            sQl[r * QSTR + c] = gQl[(size_t)r * GROW + c];
        }
    }

    float m[2] = {-1e30f, -1e30f}, l[2] = {0.f, 0.f};
    float o[16][4];
#pragma unroll
    for (int n = 0; n < 16; n++)
#pragma unroll
        for (int r = 0; r < 4; r++) o[n][r] = 0.f;

    for (int k0 = 0; k0 < SEQ; k0 += 64) {
        if (k0 >= seqlen) break;
        __syncthreads();
        {
            const uint32_t* gKh = (const uint32_t*)(Kh + (size_t)k0 * DIM + head * HDIM);
            const uint32_t* gKl = (const uint32_t*)(Kl + (size_t)k0 * DIM + head * HDIM);
            for (int i = tid; i < 64 * 64; i += 128) {
                const int r = i >> 6, c = i & 63;
                sKh[r * QSTR + c] = gKh[(size_t)r * GROW + c];
                sKl[r * QSTR + c] = gKl[(size_t)r * GROW + c];
            }
        }
        {
            const uint32_t* gVh = (const uint32_t*)(Vh + (size_t)k0 * DIM + head * HDIM);
            const uint32_t* gVl = (const uint32_t*)(Vl + (size_t)k0 * DIM + head * HDIM);
            __nv_bfloat16* tVh = (__nv_bfloat16*)sVh;
            __nv_bfloat16* tVl = (__nv_bfloat16*)sVl;
            for (int i = tid; i < 64 * 64; i += 128) {
                const int r = i >> 6, du = i & 63;
                uint32_t vh = gVh[(size_t)r * GROW + du];
                uint32_t vl = gVl[(size_t)r * GROW + du];
                __nv_bfloat162 vh2 = *reinterpret_cast<__nv_bfloat162*>(&vh);
                __nv_bfloat162 vl2 = *reinterpret_cast<__nv_bfloat162*>(&vl);
                tVh[(2 * du)     * (2 * VSTR) + r] = vh2.x;
                tVh[(2 * du + 1) * (2 * VSTR) + r] = vh2.y;
                tVl[(2 * du)     * (2 * VSTR) + r] = vl2.x;
                tVl[(2 * du + 1) * (2 * VSTR) + r] = vl2.y;
            }
        }
        __syncthreads();

        float s[8][4];
#pragma unroll
        for (int j = 0; j < 8; j++)
#pragma unroll
            for (int r = 0; r < 4; r++) s[j][r] = 0.f;

#pragma unroll
        for (int ks = 0; ks < 8; ks++) {
            uint32_t ah[4], al[4];
            const int ab = (m0 + g) * QSTR + ks * 8 + tg;
            ah[0] = sQh[ab];            ah[1] = sQh[ab + 8 * QSTR];
            ah[2] = sQh[ab + 4];        ah[3] = sQh[ab + 8 * QSTR + 4];
            al[0] = sQl[ab];            al[1] = sQl[ab + 8 * QSTR];
            al[2] = sQl[ab + 4];        al[3] = sQl[ab + 8 * QSTR + 4];
#pragma unroll
            for (int j = 0; j < 8; j++) {
                uint32_t bh[2], bl[2];
                const int kb = (8 * j + g) * QSTR + ks * 8 + tg;
                bh[0] = sKh[kb]; bh[1] = sKh[kb + 4];
                bl[0] = sKl[kb]; bl[1] = sKl[kb + 4];
                MMA_BF16(s[j], ah, bh);
                MMA_BF16(s[j], ah, bl);
                MMA_BF16(s[j], al, bh);
            }
        }

        const int kv = seqlen - k0;
        float mx0 = -1e30f, mx1 = -1e30f;
#pragma unroll
        for (int j = 0; j < 8; j++) {
            const int c0 = 8 * j + 2 * tg, c1 = c0 + 1;
            if (c0 >= kv) { s[j][0] = -1e30f; s[j][2] = -1e30f; }
            if (c1 >= kv) { s[j][1] = -1e30f; s[j][3] = -1e30f; }
            mx0 = fmaxf(mx0, fmaxf(s[j][0], s[j][1]));
            mx1 = fmaxf(mx1, fmaxf(s[j][2], s[j][3]));
        }
        mx0 = fmaxf(mx0, __shfl_xor_sync(0xffffffff, mx0, 1));
        mx0 = fmaxf(mx0, __shfl_xor_sync(0xffffffff, mx0, 2));
        mx1 = fmaxf(mx1, __shfl_xor_sync(0xffffffff, mx1, 1));
        mx1 = fmaxf(mx1, __shfl_xor_sync(0xffffffff, mx1, 2));
        const float mn0 = fmaxf(m[0], mx0);
        const float mn1 = fmaxf(m[1], mx1);
        const float a0 = __expf(m[0] - mn0);
        const float a1 = __expf(m[1] - mn1);
        m[0] = mn0; m[1] = mn1;

        float sum0 = 0.f, sum1 = 0.f;
#pragma unroll
        for (int j = 0; j < 8; j++) {
            s[j][0] = __expf(s[j][0] - mn0);
            s[j][1] = __expf(s[j][1] - mn0);
            s[j][2] = __expf(s[j][2] - mn1);
            s[j][3] = __expf(s[j][3] - mn1);
            sum0 += s[j][0] + s[j][1];
            sum1 += s[j][2] + s[j][3];
        }
        sum0 += __shfl_xor_sync(0xffffffff, sum0, 1);
        sum0 += __shfl_xor_sync(0xffffffff, sum0, 2);
        sum1 += __shfl_xor_sync(0xffffffff, sum1, 1);
        sum1 += __shfl_xor_sync(0xffffffff, sum1, 2);
        l[0] = l[0] * a0 + sum0;
        l[1] = l[1] * a1 + sum1;

#pragma unroll
        for (int n = 0; n < 16; n++) {
            o[n][0] *= a0; o[n][1] *= a0;
            o[n][2] *= a1; o[n][3] *= a1;
        }

#pragma unroll
        for (int kp = 0; kp < 4; kp++) {
            uint32_t ph[4], pl[4];
            const int j0 = 2 * kp, j1 = 2 * kp + 1;
            uint2 t;
            t = split2(s[j0][0], s[j0][1]); ph[0] = t.x; pl[0] = t.y;
            t = split2(s[j0][2], s[j0][3]); ph[1] = t.x; pl[1] = t.y;
            t = split2(s[j1][0], s[j1][1]); ph[2] = t.x; pl[2] = t.y;
            t = split2(s[j1][2], s[j1][3]); ph[3] = t.x; pl[3] = t.y;
#pragma unroll
            for (int n = 0; n < 16; n++) {
                uint32_t bh[2], bl[2];
                const int vb = (8 * n + g) * VSTR + kp * 8 + tg;
                bh[0] = sVh[vb]; bh[1] = sVh[vb + 4];
                bl[0] = sVl[vb]; bl[1] = sVl[vb + 4];
                MMA_BF16(o[n], ph, bh);
                MMA_BF16(o[n], ph, bl);
                MMA_BF16(o[n], pl, bh);
            }
        }
    }

    // epilogue: normalize, write fp16 hi/lo (feeds fp16x2 O-projection)
    const float inv0 = 1.f / l[0];
    const float inv1 = 1.f / l[1];
    const int r0 = q0 + m0 + g;
    const int r1 = r0 + 8;
    uint32_t* oHh = (uint32_t*)(Oh);
    uint32_t* oLl = (uint32_t*)(Ol);
#pragma unroll
    for (int n = 0; n < 16; n++) {
        const int col = head * HDIM + 8 * n + 2 * tg;
        uint2 p0 = split2h(o[n][0] * inv0, o[n][1] * inv0);
        oHh[(size_t)r0 * GROW + col / 2] = p0.x;
        oLl[(size_t)r0 * GROW + col / 2] = p0.y;
        uint2 p1 = split2h(o[n][2] * inv1, o[n][3] * inv1);
        oHh[(size_t)r1 * GROW + col / 2] = p1.x;
        oLl[(size_t)r1 * GROW + col / 2] = p1.y;
    }
}

// ---------------------------------------------------------------------------
// Launch  (launch #5 = QKV GEMM — that's what ncu profiles)
// ---------------------------------------------------------------------------
extern "C" void kernel_launch(void* const* d_in, const int* in_sizes, int n_in,
                              void* d_out, int out_size) {
    const float* x         = (const float*)d_in[0];
    const int*   seq_lens  = (const int*)  d_in[1];
    const int*   grid_sz   = (const int*)  d_in[2];
    const float* freqs     = (const float*)d_in[3];
    const float* wq        = (const float*)d_in[4];
    const float* bq        = (const float*)d_in[5];
    const float* wk        = (const float*)d_in[6];
    const float* bk        = (const float*)d_in[7];
    const float* wv        = (const float*)d_in[8];
    const float* bv        = (const float*)d_in[9];
    const float* wo        = (const float*)d_in[10];
    const float* bo        = (const float*)d_in[11];
    const float* gq        = (const float*)d_in[12];
    const float* gk        = (const float*)d_in[13];
    float* out = (float*)d_out;

    float *q, *k, *v;
    cudaGetSymbolAddress((void**)&q, g_q);
    cudaGetSymbolAddress((void**)&k, g_k);
    cudaGetSymbolAddress((void**)&v, g_v);

    __half *xh, *xl, *ah, *al, *hwq, *hwk, *hwv, *hwo;
    cudaGetSymbolAddress((void**)&xh,  g_xh); cudaGetSymbolAddress((void**)&xl, g_xl);
    cudaGetSymbolAddress((void**)&ah,  g_ah); cudaGetSymbolAddress((void**)&al, g_al);
    cudaGetSymbolAddress((void**)&hwq, g_wq); cudaGetSymbolAddress((void**)&hwk, g_wk);
    cudaGetSymbolAddress((void**)&hwv, g_wv); cudaGetSymbolAddress((void**)&hwo, g_wo);

    __nv_bfloat16 *qh, *ql, *kh, *kl, *vh, *vl;
    cudaGetSymbolAddress((void**)&qh, g_qh); cudaGetSymbolAddress((void**)&ql, g_ql);
    cudaGetSymbolAddress((void**)&kh, g_kh); cudaGetSymbolAddress((void**)&kl, g_kl);
    cudaGetSymbolAddress((void**)&vh, g_vh); cudaGetSymbolAddress((void**)&vl, g_vl);

    const int nX = SEQ * DIM, nW = DIM * DIM;
    const int gemm_smem = 2 * STG_BYTES;   // 61440 bytes
    cudaFuncSetAttribute(gemm_f16x2_pipe,
                         cudaFuncAttributeMaxDynamicSharedMemorySize, gemm_smem);

    // launches 1-4
    split_f16<<<nX / 1024, 256>>>(x, xh, xl, nX);
    round_f16<<<nW / 1024, 256>>>(wq, hwq, nW);
    round_f16<<<nW / 1024, 256>>>(wk, hwk, nW);
    round_f16<<<nW / 1024, 256>>>(wv, hwv, nW);

    // launch 5: fused QKV GEMM (profiled by ncu)
    GemmF16Batch qkv;
    qkv.B[0] = hwq; qkv.bias[0] = bq; qkv.C[0] = q;
    qkv.B[1] = hwk; qkv.bias[1] = bk; qkv.C[1] = k;
    qkv.B[2] = hwv; qkv.bias[2] = bv; qkv.C[2] = v;
    gemm_f16x2_pipe<<<dim3(DIM / 128, SEQ / 128, 3), 256, gemm_smem>>>(
        xh, xl, qkv, SEQ, DIM, DIM);

    round_f16<<<nW / 1024, 256>>>(wo, hwo, nW);

    const float scale = 0.08838834764831845f;   // 1/sqrt(128)
    norm_rope_split<<<SEQ, 256>>>(q, gq, freqs, grid_sz, qh, ql, scale);
    norm_rope_split<<<SEQ, 256>>>(k, gk, freqs, grid_sz, kh, kl, 1.0f);
    split_f32<<<nX / 1024, 256>>>(v, vh, vl, nX);

    const size_t fl_smem = (size_t)(4 * 64 * QSTR + 2 * 128 * VSTR) * sizeof(uint32_t);
    cudaFuncSetAttribute(flash_mma, cudaFuncAttributeMaxDynamicSharedMemorySize, (int)fl_smem);
    flash_mma<<<dim3(SEQ / 64, NHEADS), 128, fl_smem>>>(qh, ql, kh, kl, vh, vl,
                                                        seq_lens, ah, al);

    GemmF16Batch ob;
    ob.B[0] = hwo; ob.bias[0] = bo; ob.C[0] = out;
    ob.B[1] = hwo; ob.bias[1] = bo; ob.C[1] = out;
    ob.B[2] = hwo; ob.bias[2] = bo; ob.C[2] = out;
    gemm_f16x2_pipe<<<dim3(DIM / 128, SEQ / 128, 1), 256, gemm_smem>>>(
        ah, al, ob, SEQ, DIM, DIM);
}

// round 11
// speedup vs baseline: 2.9501x; 1.0850x over previous
#include <cuda_runtime.h>
#include <cuda_bf16.h>
#include <cuda_fp16.h>
#include <math.h>
#include <stdint.h>

#define DIM    3072
#define NHEADS 24
#define HDIM   128
#define SEQ    2304

// ---------------------------------------------------------------------------
// Scratch (allocation-free: __device__ globals)
// ---------------------------------------------------------------------------
__device__ float g_q[SEQ * DIM];
__device__ float g_k[SEQ * DIM];
__device__ float g_v[SEQ * DIM];

__device__ __half g_xh[SEQ * DIM], g_xl[SEQ * DIM];     // x  fp16 hi/lo
__device__ __half g_ah[SEQ * DIM], g_al[SEQ * DIM];     // attn fp16 hi/lo
__device__ __half g_wq[DIM * DIM], g_wk[DIM * DIM];     // weights single fp16
__device__ __half g_wv[DIM * DIM], g_wo[DIM * DIM];

__device__ __half g_qh[SEQ * DIM], g_ql[SEQ * DIM];     // Q fp16 hi/lo
__device__ __half g_kh[SEQ * DIM], g_kl[SEQ * DIM];     // K fp16 (hi used)
__device__ __half g_vh[SEQ * DIM], g_vl[SEQ * DIM];     // V fp16 hi/lo

// fp32 pair -> packed fp16 hi / fp16 lo
__device__ __forceinline__ uint2 split2h(float a, float b) {
    __half2 h = __floats2half2_rn(a, b);
    __half2 l = __floats2half2_rn(a - __half2float(__low2half(h)),
                                  b - __half2float(__high2half(h)));
    uint2 r;
    r.x = *reinterpret_cast<uint32_t*>(&h);
    r.y = *reinterpret_cast<uint32_t*>(&l);
    return r;
}

__device__ __forceinline__ uint32_t pack2h(float a, float b) {
    __half2 h = __floats2half2_rn(a, b);
    return *reinterpret_cast<uint32_t*>(&h);
}

__device__ __forceinline__ void cp16(uint32_t saddr, const void* gptr) {
    asm volatile("cp.async.cg.shared.global [%0], [%1], 16;"
                 :: "r"(saddr), "l"(gptr));
}

#define MMA_F16(d, a, b)                                                      \
    asm volatile("mma.sync.aligned.m16n8k16.row.col.f32.f16.f16.f32 "         \
                 "{%0,%1,%2,%3}, {%4,%5,%6,%7}, {%8,%9}, {%0,%1,%2,%3};"      \
                 : "+f"(d[0]), "+f"(d[1]), "+f"(d[2]), "+f"(d[3])             \
                 : "r"(a[0]), "r"(a[1]), "r"(a[2]), "r"(a[3]),                \
                   "r"(b[0]), "r"(b[1]))

// ---------------------------------------------------------------------------
// fp32 -> (fp16 hi, fp16 lo) split.
// ---------------------------------------------------------------------------
__global__ __launch_bounds__(256)
void split_f16(const float* __restrict__ in, __half* __restrict__ hi,
               __half* __restrict__ lo, int n) {
    int i = (blockIdx.x * 256 + threadIdx.x) * 4;
    if (i + 3 >= n) return;
    float4 v = *(const float4*)(in + i);
    uint2 p0 = split2h(v.x, v.y);
    uint2 p1 = split2h(v.z, v.w);
    *(uint2*)(hi + i) = make_uint2(p0.x, p1.x);
    *(uint2*)(lo + i) = make_uint2(p0.y, p1.y);
}

// ---------------------------------------------------------------------------
// fp32 -> fp16 (single, round-to-nearest).
// ---------------------------------------------------------------------------
__global__ __launch_bounds__(256)
void round_f16(const float* __restrict__ in, __half* __restrict__ out, int n) {
    int i = (blockIdx.x * 256 + threadIdx.x) * 4;
    if (i + 3 >= n) return;
    float4 v = *(const float4*)(in + i);
    __half2 h0 = __floats2half2_rn(v.x, v.y);
    __half2 h1 = __floats2half2_rn(v.z, v.w);
    *(uint2*)(out + i) = make_uint2(*reinterpret_cast<uint32_t*>(&h0),
                                    *reinterpret_cast<uint32_t*>(&h1));
}

// ---------------------------------------------------------------------------
// fp16x2 GEMM (NT): C = (Ah+Al) . B + bias.  2 MMA passes. (unchanged, R10)
// ---------------------------------------------------------------------------
#define SSTR 20
#define ARR_U32 (128 * SSTR)
#define STG_U32 (3 * ARR_U32)
#define ARR_BYTES (ARR_U32 * 4)
#define STG_BYTES (STG_U32 * 4)

struct GemmF16Batch {
    const __half* B[3];
    const float*  bias[3];
    float*        C[3];
};

__global__ __launch_bounds__(256, 2)
void gemm_f16x2_pipe(const __half* __restrict__ Ah,
                     const __half* __restrict__ Al,
                     GemmF16Batch batch, int M, int N, int K) {
    extern __shared__ uint32_t smem[];
    const uint32_t sbase = (uint32_t)__cvta_generic_to_shared(smem);

    const __half* __restrict__ B = batch.B[blockIdx.z];
    const float* __restrict__ bias = batch.bias[blockIdx.z];
    float* __restrict__ C = batch.C[blockIdx.z];

    const int bm = blockIdx.y * 128, bn = blockIdx.x * 128;
    const int tid = threadIdx.x;
    const int w = tid >> 5, lane = tid & 31;
    const int wm = w & 1, wn = w >> 1;
    const int g = lane >> 2, tg = lane & 3;

    float acc[4][4][4];
#pragma unroll
    for (int mi = 0; mi < 4; mi++)
#pragma unroll
        for (int ni = 0; ni < 4; ni++)
#pragma unroll
            for (int r = 0; r < 4; r++) acc[mi][ni][r] = 0.f;

    auto issue = [&](int kt, int stage) {
        const uint32_t sb = sbase + (uint32_t)stage * STG_BYTES;
#pragma unroll
        for (int i = 0; i < 6; i++) {
            const int c = tid + i * 256;
            const int arr = c >> 9;
            const int cid = c & 511;
            const int r = cid >> 2, q = cid & 3;
            const uint32_t dst = sb + arr * ARR_BYTES + (r * SSTR + q * 4) * 4;
            const __half* src;
            if      (arr == 0) src = Ah + (size_t)(bm + r) * K + kt + q * 8;
            else if (arr == 1) src = Al + (size_t)(bm + r) * K + kt + q * 8;
            else               src = B  + (size_t)(bn + r) * K + kt + q * 8;
            cp16(dst, src);
        }
    };

    const int ntiles = K / 32;
    issue(0, 0);
    asm volatile("cp.async.commit_group;");

    for (int t = 0; t < ntiles; t++) {
        if (t + 1 < ntiles) issue((t + 1) * 32, (t + 1) & 1);
        asm volatile("cp.async.commit_group;");
        asm volatile("cp.async.wait_group 1;");
        __syncthreads();

        const uint32_t* sAh = smem + (t & 1) * STG_U32;
        const uint32_t* sAl = sAh + ARR_U32;
        const uint32_t* sB  = sAl + ARR_U32;

#pragma unroll
        for (int ks = 0; ks < 2; ks++) {
            const int kb = ks * 8;
            uint32_t ah[4][4], al[4][4], bf[4][2];
#pragma unroll
            for (int mi = 0; mi < 4; mi++) {
                const int r = wm * 64 + mi * 16 + g;
                ah[mi][0] = sAh[r * SSTR + kb + tg];
                ah[mi][1] = sAh[(r + 8) * SSTR + kb + tg];
                ah[mi][2] = sAh[r * SSTR + kb + tg + 4];
                ah[mi][3] = sAh[(r + 8) * SSTR + kb + tg + 4];
                al[mi][0] = sAl[r * SSTR + kb + tg];
                al[mi][1] = sAl[(r + 8) * SSTR + kb + tg];
                al[mi][2] = sAl[r * SSTR + kb + tg + 4];
                al[mi][3] = sAl[(r + 8) * SSTR + kb + tg + 4];
            }
#pragma unroll
            for (int ni = 0; ni < 4; ni++) {
                const int c = wn * 32 + ni * 8 + g;
                bf[ni][0] = sB[c * SSTR + kb + tg];
                bf[ni][1] = sB[c * SSTR + kb + tg + 4];
            }
#pragma unroll
            for (int mi = 0; mi < 4; mi++)
#pragma unroll
                for (int ni = 0; ni < 4; ni++) {
                    MMA_F16(acc[mi][ni], ah[mi], bf[ni]);
                    MMA_F16(acc[mi][ni], al[mi], bf[ni]);
                }
        }
        __syncthreads();
    }

#pragma unroll
    for (int mi = 0; mi < 4; mi++)
#pragma unroll
        for (int ni = 0; ni < 4; ni++) {
            const int r = bm + wm * 64 + mi * 16 + g;
            const int c = bn + wn * 32 + ni * 8 + tg * 2;
            const float b0 = bias[c], b1 = bias[c + 1];
            C[(size_t)r * N + c]           = acc[mi][ni][0] + b0;
            C[(size_t)r * N + c + 1]       = acc[mi][ni][1] + b1;
            C[(size_t)(r + 8) * N + c]     = acc[mi][ni][2] + b0;
            C[(size_t)(r + 8) * N + c + 1] = acc[mi][ni][3] + b1;
        }
}

// ---------------------------------------------------------------------------
// Fused fp32 RMSNorm + 3-axis RoPE + scale + fp16 hi/lo split.
// ---------------------------------------------------------------------------
__global__ __launch_bounds__(256)
void norm_rope_split(const float* __restrict__ buf, const float* __restrict__ g,
                     const float* __restrict__ freqs,
                     const int* __restrict__ grid_sizes,
                     __half* __restrict__ oh, __half* __restrict__ ol,
                     float scale) {
    __shared__ float red[256];
    __shared__ float s_rn;
    const int row = blockIdx.x;
    const int tid = threadIdx.x;
    const float* rp = buf + (size_t)row * DIM;

    float ss = 0.f;
    for (int i = tid; i < DIM; i += 256) { float v = rp[i]; ss += v * v; }
    red[tid] = ss;
    __syncthreads();
#pragma unroll
    for (int st = 128; st > 0; st >>= 1) {
        if (tid < st) red[tid] += red[tid + st];
        __syncthreads();
    }
    if (tid == 0) s_rn = rsqrtf(red[0] / (float)DIM + 1e-6f);
    __syncthreads();
    const float rn = s_rn;

    const int gh = grid_sizes[1];
    const int gw = grid_sizes[2];
    const int fi = row / (gh * gw);
    const int hi = (row % (gh * gw)) / gw;
    const int wi = row % gw;

    for (int p = tid; p < DIM / 2; p += 256) {
        const int c = p & 63;
        const int pos = (c < 22) ? fi : ((c < 43) ? hi : wi);
        const float theta = freqs[pos * 64 + c];
        float sn, cs;
        sincosf(theta, &sn, &cs);
        const int idx = (p >> 6) * HDIM + 2 * c;
        const float xr = rp[idx]     * rn * g[idx];
        const float xi = rp[idx + 1] * rn * g[idx + 1];
        const float y0 = (xr * cs - xi * sn) * scale;
        const float y1 = (xr * sn + xi * cs) * scale;
        uint2 p2 = split2h(y0, y1);
        *(uint32_t*)(oh + (size_t)row * DIM + idx) = p2.x;
        *(uint32_t*)(ol + (size_t)row * DIM + idx) = p2.y;
    }
}

// ---------------------------------------------------------------------------
// Tensor-core flash attention, fp16x2 (2 passes per matmul).
// QK^T: (Qh+Ql) . K ; PV: P . (Vh+Vl).  fp32 online softmax.
// BQ=64, BK=64, D=128. 128 threads = 4 warps; warp w owns q-rows [16w,16w+16).
// Epilogue writes fp16 hi/lo for the fp16x2 O-projection.
// ---------------------------------------------------------------------------
#define QSTR 68   // u32 stride for Q/K smem rows (64 data + 4 pad)
#define VSTR 35   // u32 stride for V^T smem rows (32 data + 3 pad)

__global__ __launch_bounds__(128, 2)
void flash_f16(const __half* __restrict__ Qh, const __half* __restrict__ Ql,
               const __half* __restrict__ K,
               const __half* __restrict__ Vh, const __half* __restrict__ Vl,
               const int* __restrict__ seq_lens,
               __half* __restrict__ Oh, __half* __restrict__ Ol) {
    extern __shared__ uint32_t sm[];
    uint32_t* sQh = sm;
    uint32_t* sQl = sQh + 64 * QSTR;
    uint32_t* sK  = sQl + 64 * QSTR;
    uint32_t* sVh = sK  + 64 * QSTR;          // [128][VSTR] (V transposed)
    uint32_t* sVl = sVh + 128 * VSTR;

    const int head = blockIdx.y;
    const int q0 = blockIdx.x * 64;
    const int tid = threadIdx.x;
    const int w = tid >> 5, lane = tid & 31;
    const int g = lane >> 2, tg = lane & 3;
    const int m0 = w * 16;
    const int seqlen = seq_lens[0];
    const int GROW = DIM / 2;

    // ---- load Q tile (fp16 hi/lo) ----
    {
        const uint32_t* gQh = (const uint32_t*)(Qh + (size_t)q0 * DIM + head * HDIM);
        const uint32_t* gQl = (const uint32_t*)(Ql + (size_t)q0 * DIM + head * HDIM);
        for (int i = tid; i < 64 * 64; i += 128) {
            const int r = i >> 6, c = i & 63;
            sQh[r * QSTR + c] = gQh[(size_t)r * GROW + c];
            sQl[r * QSTR + c] = gQl[(size_t)r * GROW + c];
        }
    }

    float m[2] = {-1e30f, -1e30f}, l[2] = {0.f, 0.f};
    float o[16][4];
#pragma unroll
    for (int n = 0; n < 16; n++)
#pragma unroll
        for (int r = 0; r < 4; r++) o[n][r] = 0.f;

    for (int k0 = 0; k0 < SEQ; k0 += 64) {
        if (k0 >= seqlen) break;
        __syncthreads();
        // ---- load K tile (single fp16) ----
        {
            const uint32_t* gK = (const uint32_t*)(K + (size_t)k0 * DIM + head * HDIM);
            for (int i = tid; i < 64 * 64; i += 128) {
                const int r = i >> 6, c = i & 63;
                sK[r * QSTR + c] = gK[(size_t)r * GROW + c];
            }
        }
        // ---- load V tile (fp16 hi/lo), transpose into [dim][kv] ----
        {
            const uint32_t* gVh = (const uint32_t*)(Vh + (size_t)k0 * DIM + head * HDIM);
            const uint32_t* gVl = (const uint32_t*)(Vl + (size_t)k0 * DIM + head * HDIM);
            __half* tVh = (__half*)sVh;
            __half* tVl = (__half*)sVl;
            for (int i = tid; i < 64 * 64; i += 128) {
                const int r = i >> 6, du = i & 63;
                uint32_t vh = gVh[(size_t)r * GROW + du];
                uint32_t vl = gVl[(size_t)r * GROW + du];
                __half2 vh2 = *reinterpret_cast<__half2*>(&vh);
                __half2 vl2 = *reinterpret_cast<__half2*>(&vl);
                tVh[(2 * du)     * (2 * VSTR) + r] = __low2half(vh2);
                tVh[(2 * du + 1) * (2 * VSTR) + r] = __high2half(vh2);
                tVl[(2 * du)     * (2 * VSTR) + r] = __low2half(vl2);
                tVl[(2 * du + 1) * (2 * VSTR) + r] = __high2half(vl2);
            }
        }
        __syncthreads();

        // ---- scores S = (Qh+Ql) K^T  (2 passes) ----
        float s[8][4];
#pragma unroll
        for (int j = 0; j < 8; j++)
#pragma unroll
            for (int r = 0; r < 4; r++) s[j][r] = 0.f;

#pragma unroll
        for (int ks = 0; ks < 8; ks++) {
            uint32_t ah[4], al[4];
            const int ab = (m0 + g) * QSTR + ks * 8 + tg;
            ah[0] = sQh[ab];            ah[1] = sQh[ab + 8 * QSTR];
            ah[2] = sQh[ab + 4];        ah[3] = sQh[ab + 8 * QSTR + 4];
            al[0] = sQl[ab];            al[1] = sQl[ab + 8 * QSTR];
            al[2] = sQl[ab + 4];        al[3] = sQl[ab + 8 * QSTR + 4];
#pragma unroll
            for (int j = 0; j < 8; j++) {
                uint32_t bf[2];
                const int kb = (8 * j + g) * QSTR + ks * 8 + tg;
                bf[0] = sK[kb]; bf[1] = sK[kb + 4];
                MMA_F16(s[j], ah, bf);
                MMA_F16(s[j], al, bf);
            }
        }

        // ---- online softmax (rows m0+g and m0+g+8, warp-local) ----
        const int kv = seqlen - k0;
        float mx0 = -1e30f, mx1 = -1e30f;
#pragma unroll
        for (int j = 0; j < 8; j++) {
            const int c0 = 8 * j + 2 * tg, c1 = c0 + 1;
            if (c0 >= kv) { s[j][0] = -1e30f; s[j][2] = -1e30f; }
            if (c1 >= kv) { s[j][1] = -1e30f; s[j][3] = -1e30f; }
            mx0 = fmaxf(mx0, fmaxf(s[j][0], s[j][1]));
            mx1 = fmaxf(mx1, fmaxf(s[j][2], s[j][3]));
        }
        mx0 = fmaxf(mx0, __shfl_xor_sync(0xffffffff, mx0, 1));
        mx0 = fmaxf(mx0, __shfl_xor_sync(0xffffffff, mx0, 2));
        mx1 = fmaxf(mx1, __shfl_xor_sync(0xffffffff, mx1, 1));
        mx1 = fmaxf(mx1, __shfl_xor_sync(0xffffffff, mx1, 2));
        const float mn0 = fmaxf(m[0], mx0);
        const float mn1 = fmaxf(m[1], mx1);
        const float a0 = __expf(m[0] - mn0);
        const float a1 = __expf(m[1] - mn1);
        m[0] = mn0; m[1] = mn1;

        float sum0 = 0.f, sum1 = 0.f;
#pragma unroll
        for (int j = 0; j < 8; j++) {
            s[j][0] = __expf(s[j][0] - mn0);
            s[j][1] = __expf(s[j][1] - mn0);
            s[j][2] = __expf(s[j][2] - mn1);
            s[j][3] = __expf(s[j][3] - mn1);
            sum0 += s[j][0] + s[j][1];
            sum1 += s[j][2] + s[j][3];
        }
        sum0 += __shfl_xor_sync(0xffffffff, sum0, 1);
        sum0 += __shfl_xor_sync(0xffffffff, sum0, 2);
        sum1 += __shfl_xor_sync(0xffffffff, sum1, 1);
        sum1 += __shfl_xor_sync(0xffffffff, sum1, 2);
        l[0] = l[0] * a0 + sum0;
        l[1] = l[1] * a1 + sum1;

#pragma unroll
        for (int n = 0; n < 16; n++) {
            o[n][0] *= a0; o[n][1] *= a0;
            o[n][2] *= a1; o[n][3] *= a1;
        }

        // ---- O += P (Vh+Vl)  (P single fp16, 2 passes) ----
#pragma unroll
        for (int kp = 0; kp < 4; kp++) {
            uint32_t ph[4];
            const int j0 = 2 * kp, j1 = 2 * kp + 1;
            ph[0] = pack2h(s[j0][0], s[j0][1]);
            ph[1] = pack2h(s[j0][2], s[j0][3]);
            ph[2] = pack2h(s[j1][0], s[j1][1]);
            ph[3] = pack2h(s[j1][2], s[j1][3]);
#pragma unroll
            for (int n = 0; n < 16; n++) {
                uint32_t bh[2], bl[2];
                const int vb = (8 * n + g) * VSTR + kp * 8 + tg;
                bh[0] = sVh[vb]; bh[1] = sVh[vb + 4];
                bl[0] = sVl[vb]; bl[1] = sVl[vb + 4];
                MMA_F16(o[n], ph, bh);
                MMA_F16(o[n], ph, bl);
            }
        }
    }

    // ---- epilogue: normalize, write fp16 hi/lo ----
    const float inv0 = 1.f / l[0];
    const float inv1 = 1.f / l[1];
    const int r0 = q0 + m0 + g;
    const int r1 = r0 + 8;
    uint32_t* oHh = (uint32_t*)(Oh);
    uint32_t* oLl = (uint32_t*)(Ol);
#pragma unroll
    for (int n = 0; n < 16; n++) {
        const int col = head * HDIM + 8 * n + 2 * tg;
        uint2 p0 = split2h(o[n][0] * inv0, o[n][1] * inv0);
        oHh[(size_t)r0 * GROW + col / 2] = p0.x;
        oLl[(size_t)r0 * GROW + col / 2] = p0.y;
        uint2 p1 = split2h(o[n][2] * inv1, o[n][3] * inv1);
        oHh[(size_t)r1 * GROW + col / 2] = p1.x;
        oLl[(size_t)r1 * GROW + col / 2] = p1.y;
    }
}

// ---------------------------------------------------------------------------
// Launch  (launch #5 = QKV GEMM — that's what ncu profiles)
// ---------------------------------------------------------------------------
extern "C" void kernel_launch(void* const* d_in, const int* in_sizes, int n_in,
                              void* d_out, int out_size) {
    const float* x         = (const float*)d_in[0];
    const int*   seq_lens  = (const int*)  d_in[1];
    const int*   grid_sz   = (const int*)  d_in[2];
    const float* freqs     = (const float*)d_in[3];
    const float* wq        = (const float*)d_in[4];
    const float* bq        = (const float*)d_in[5];
    const float* wk        = (const float*)d_in[6];
    const float* bk        = (const float*)d_in[7];
    const float* wv        = (const float*)d_in[8];
    const float* bv        = (const float*)d_in[9];
    const float* wo        = (const float*)d_in[10];
    const float* bo        = (const float*)d_in[11];
    const float* gq        = (const float*)d_in[12];
    const float* gk        = (const float*)d_in[13];
    float* out = (float*)d_out;

    float *q, *k, *v;
    cudaGetSymbolAddress((void**)&q, g_q);
    cudaGetSymbolAddress((void**)&k, g_k);
    cudaGetSymbolAddress((void**)&v, g_v);

    __half *xh, *xl, *ah, *al, *hwq, *hwk, *hwv, *hwo;
    cudaGetSymbolAddress((void**)&xh,  g_xh); cudaGetSymbolAddress((void**)&xl, g_xl);
    cudaGetSymbolAddress((void**)&ah,  g_ah); cudaGetSymbolAddress((void**)&al, g_al);
    cudaGetSymbolAddress((void**)&hwq, g_wq); cudaGetSymbolAddress((void**)&hwk, g_wk);
    cudaGetSymbolAddress((void**)&hwv, g_wv); cudaGetSymbolAddress((void**)&hwo, g_wo);

    __half *qh, *ql, *kh, *kl, *vh, *vl;
    cudaGetSymbolAddress((void**)&qh, g_qh); cudaGetSymbolAddress((void**)&ql, g_ql);
    cudaGetSymbolAddress((void**)&kh, g_kh); cudaGetSymbolAddress((void**)&kl, g_kl);
    cudaGetSymbolAddress((void**)&vh, g_vh); cudaGetSymbolAddress((void**)&vl, g_vl);

    const int nX = SEQ * DIM, nW = DIM * DIM;
    const int gemm_smem = 2 * STG_BYTES;   // 61440 bytes
    cudaFuncSetAttribute(gemm_f16x2_pipe,
                         cudaFuncAttributeMaxDynamicSharedMemorySize, gemm_smem);

    // launches 1-4
    split_f16<<<nX / 1024, 256>>>(x, xh, xl, nX);
    round_f16<<<nW / 1024, 256>>>(wq, hwq, nW);
    round_f16<<<nW / 1024, 256>>>(wk, hwk, nW);
    round_f16<<<nW / 1024, 256>>>(wv, hwv, nW);

    // launch 5: fused QKV GEMM (profiled by ncu)
    GemmF16Batch qkv;
    qkv.B[0] = hwq; qkv.bias[0] = bq; qkv.C[0] = q;
    qkv.B[1] = hwk; qkv.bias[1] = bk; qkv.C[1] = k;
    qkv.B[2] = hwv; qkv.bias[2] = bv; qkv.C[2] = v;
    gemm_f16x2_pipe<<<dim3(DIM / 128, SEQ / 128, 3), 256, gemm_smem>>>(
        xh, xl, qkv, SEQ, DIM, DIM);

    round_f16<<<nW / 1024, 256>>>(wo, hwo, nW);

    const float scale = 0.08838834764831845f;   // 1/sqrt(128)
    norm_rope_split<<<SEQ, 256>>>(q, gq, freqs, grid_sz, qh, ql, scale);
    norm_rope_split<<<SEQ, 256>>>(k, gk, freqs, grid_sz, kh, kl, 1.0f);
    split_f16<<<nX / 1024, 256>>>(v, vh, vl, nX);

    const size_t fl_smem = (size_t)(3 * 64 * QSTR + 2 * 128 * VSTR) * sizeof(uint32_t);
    cudaFuncSetAttribute(flash_f16, cudaFuncAttributeMaxDynamicSharedMemorySize, (int)fl_smem);
    flash_f16<<<dim3(SEQ / 64, NHEADS), 128, fl_smem>>>(qh, ql, kh, vh, vl,
                                                        seq_lens, ah, al);

    GemmF16Batch ob;
    ob.B[0] = hwo; ob.bias[0] = bo; ob.C[0] = out;
    ob.B[1] = hwo; ob.bias[1] = bo; ob.C[1] = out;
    ob.B[2] = hwo; ob.bias[2] = bo; ob.C[2] = out;
    gemm_f16x2_pipe<<<dim3(DIM / 128, SEQ / 128, 1), 256, gemm_smem>>>(
        ah, al, ob, SEQ, DIM, DIM);
}

// round 12
// speedup vs baseline: 3.8083x; 1.2909x over previous
#include <cuda_runtime.h>
#include <cuda_fp16.h>
#include <math.h>
#include <stdint.h>

#define DIM    3072
#define NHEADS 24
#define HDIM   128
#define SEQ    2304

// ---------------------------------------------------------------------------
// Scratch (allocation-free: __device__ globals)
// ---------------------------------------------------------------------------
__device__ float g_q[SEQ * DIM];
__device__ float g_k[SEQ * DIM];
__device__ float g_v[SEQ * DIM];

__device__ __half g_xh[SEQ * DIM], g_xl[SEQ * DIM];     // x  fp16 hi/lo
__device__ __half g_ah[SEQ * DIM], g_al[SEQ * DIM];     // attn fp16 hi/lo
__device__ __half g_wq[DIM * DIM], g_wk[DIM * DIM];     // weights single fp16
__device__ __half g_wv[DIM * DIM], g_wo[DIM * DIM];

__device__ __half g_qs[SEQ * DIM];                      // Q single fp16
__device__ __half g_ks[SEQ * DIM];                      // K single fp16
__device__ __half g_vs[SEQ * DIM];                      // V single fp16

// fp32 pair -> packed fp16 hi / fp16 lo
__device__ __forceinline__ uint2 split2h(float a, float b) {
    __half2 h = __floats2half2_rn(a, b);
    __half2 l = __floats2half2_rn(a - __half2float(__low2half(h)),
                                  b - __half2float(__high2half(h)));
    uint2 r;
    r.x = *reinterpret_cast<uint32_t*>(&h);
    r.y = *reinterpret_cast<uint32_t*>(&l);
    return r;
}

__device__ __forceinline__ uint32_t pack2h(float a, float b) {
    __half2 h = __floats2half2_rn(a, b);
    return *reinterpret_cast<uint32_t*>(&h);
}

__device__ __forceinline__ void cp16(uint32_t saddr, const void* gptr) {
    asm volatile("cp.async.cg.shared.global [%0], [%1], 16;"
                 :: "r"(saddr), "l"(gptr));
}

#define MMA_F16(d, a, b)                                                      \
    asm volatile("mma.sync.aligned.m16n8k16.row.col.f32.f16.f16.f32 "         \
                 "{%0,%1,%2,%3}, {%4,%5,%6,%7}, {%8,%9}, {%0,%1,%2,%3};"      \
                 : "+f"(d[0]), "+f"(d[1]), "+f"(d[2]), "+f"(d[3])             \
                 : "r"(a[0]), "r"(a[1]), "r"(a[2]), "r"(a[3]),                \
                   "r"(b[0]), "r"(b[1]))

// ---------------------------------------------------------------------------
// fp32 -> (fp16 hi, fp16 lo) split.
// ---------------------------------------------------------------------------
__global__ __launch_bounds__(256)
void split_f16(const float* __restrict__ in, __half* __restrict__ hi,
               __half* __restrict__ lo, int n) {
    int i = (blockIdx.x * 256 + threadIdx.x) * 4;
    if (i + 3 >= n) return;
    float4 v = *(const float4*)(in + i);
    uint2 p0 = split2h(v.x, v.y);
    uint2 p1 = split2h(v.z, v.w);
    *(uint2*)(hi + i) = make_uint2(p0.x, p1.x);
    *(uint2*)(lo + i) = make_uint2(p0.y, p1.y);
}

// ---------------------------------------------------------------------------
// fp32 -> fp16 (single, round-to-nearest).
// ---------------------------------------------------------------------------
__global__ __launch_bounds__(256)
void round_f16(const float* __restrict__ in, __half* __restrict__ out, int n) {
    int i = (blockIdx.x * 256 + threadIdx.x) * 4;
    if (i + 3 >= n) return;
    float4 v = *(const float4*)(in + i);
    __half2 h0 = __floats2half2_rn(v.x, v.y);
    __half2 h1 = __floats2half2_rn(v.z, v.w);
    *(uint2*)(out + i) = make_uint2(*reinterpret_cast<uint32_t*>(&h0),
                                    *reinterpret_cast<uint32_t*>(&h1));
}

// ---------------------------------------------------------------------------
// fp16x2 GEMM (NT): C = (Ah+Al) . B + bias.  2 MMA passes. (unchanged, R10)
// ---------------------------------------------------------------------------
#define SSTR 20
#define ARR_U32 (128 * SSTR)
#define STG_U32 (3 * ARR_U32)
#define ARR_BYTES (ARR_U32 * 4)
#define STG_BYTES (STG_U32 * 4)

struct GemmF16Batch {
    const __half* B[3];
    const float*  bias[3];
    float*        C[3];
};

__global__ __launch_bounds__(256, 2)
void gemm_f16x2_pipe(const __half* __restrict__ Ah,
                     const __half* __restrict__ Al,
                     GemmF16Batch batch, int M, int N, int K) {
    extern __shared__ uint32_t smem[];
    const uint32_t sbase = (uint32_t)__cvta_generic_to_shared(smem);

    const __half* __restrict__ B = batch.B[blockIdx.z];
    const float* __restrict__ bias = batch.bias[blockIdx.z];
    float* __restrict__ C = batch.C[blockIdx.z];

    const int bm = blockIdx.y * 128, bn = blockIdx.x * 128;
    const int tid = threadIdx.x;
    const int w = tid >> 5, lane = tid & 31;
    const int wm = w & 1, wn = w >> 1;
    const int g = lane >> 2, tg = lane & 3;

    float acc[4][4][4];
#pragma unroll
    for (int mi = 0; mi < 4; mi++)
#pragma unroll
        for (int ni = 0; ni < 4; ni++)
#pragma unroll
            for (int r = 0; r < 4; r++) acc[mi][ni][r] = 0.f;

    auto issue = [&](int kt, int stage) {
        const uint32_t sb = sbase + (uint32_t)stage * STG_BYTES;
#pragma unroll
        for (int i = 0; i < 6; i++) {
            const int c = tid + i * 256;
            const int arr = c >> 9;
            const int cid = c & 511;
            const int r = cid >> 2, q = cid & 3;
            const uint32_t dst = sb + arr * ARR_BYTES + (r * SSTR + q * 4) * 4;
            const __half* src;
            if      (arr == 0) src = Ah + (size_t)(bm + r) * K + kt + q * 8;
            else if (arr == 1) src = Al + (size_t)(bm + r) * K + kt + q * 8;
            else               src = B  + (size_t)(bn + r) * K + kt + q * 8;
            cp16(dst, src);
        }
    };

    const int ntiles = K / 32;
    issue(0, 0);
    asm volatile("cp.async.commit_group;");

    for (int t = 0; t < ntiles; t++) {
        if (t + 1 < ntiles) issue((t + 1) * 32, (t + 1) & 1);
        asm volatile("cp.async.commit_group;");
        asm volatile("cp.async.wait_group 1;");
        __syncthreads();

        const uint32_t* sAh = smem + (t & 1) * STG_U32;
        const uint32_t* sAl = sAh + ARR_U32;
        const uint32_t* sB  = sAl + ARR_U32;

#pragma unroll
        for (int ks = 0; ks < 2; ks++) {
            const int kb = ks * 8;
            uint32_t ah[4][4], al[4][4], bf[4][2];
#pragma unroll
            for (int mi = 0; mi < 4; mi++) {
                const int r = wm * 64 + mi * 16 + g;
                ah[mi][0] = sAh[r * SSTR + kb + tg];
                ah[mi][1] = sAh[(r + 8) * SSTR + kb + tg];
                ah[mi][2] = sAh[r * SSTR + kb + tg + 4];
                ah[mi][3] = sAh[(r + 8) * SSTR + kb + tg + 4];
                al[mi][0] = sAl[r * SSTR + kb + tg];
                al[mi][1] = sAl[(r + 8) * SSTR + kb + tg];
                al[mi][2] = sAl[r * SSTR + kb + tg + 4];
                al[mi][3] = sAl[(r + 8) * SSTR + kb + tg + 4];
            }
#pragma unroll
            for (int ni = 0; ni < 4; ni++) {
                const int c = wn * 32 + ni * 8 + g;
                bf[ni][0] = sB[c * SSTR + kb + tg];
                bf[ni][1] = sB[c * SSTR + kb + tg + 4];
            }
#pragma unroll
            for (int mi = 0; mi < 4; mi++)
#pragma unroll
                for (int ni = 0; ni < 4; ni++) {
                    MMA_F16(acc[mi][ni], ah[mi], bf[ni]);
                    MMA_F16(acc[mi][ni], al[mi], bf[ni]);
                }
        }
        __syncthreads();
    }

#pragma unroll
    for (int mi = 0; mi < 4; mi++)
#pragma unroll
        for (int ni = 0; ni < 4; ni++) {
            const int r = bm + wm * 64 + mi * 16 + g;
            const int c = bn + wn * 32 + ni * 8 + tg * 2;
            const float b0 = bias[c], b1 = bias[c + 1];
            C[(size_t)r * N + c]           = acc[mi][ni][0] + b0;
            C[(size_t)r * N + c + 1]       = acc[mi][ni][1] + b1;
            C[(size_t)(r + 8) * N + c]     = acc[mi][ni][2] + b0;
            C[(size_t)(r + 8) * N + c + 1] = acc[mi][ni][3] + b1;
        }
}

// ---------------------------------------------------------------------------
// Fused fp32 RMSNorm + 3-axis RoPE + scale -> single fp16 output.
// ---------------------------------------------------------------------------
__global__ __launch_bounds__(256)
void norm_rope_pack(const float* __restrict__ buf, const float* __restrict__ g,
                    const float* __restrict__ freqs,
                    const int* __restrict__ grid_sizes,
                    __half* __restrict__ o, float scale) {
    __shared__ float red[256];
    __shared__ float s_rn;
    const int row = blockIdx.x;
    const int tid = threadIdx.x;
    const float* rp = buf + (size_t)row * DIM;

    float ss = 0.f;
    for (int i = tid; i < DIM; i += 256) { float v = rp[i]; ss += v * v; }
    red[tid] = ss;
    __syncthreads();
#pragma unroll
    for (int st = 128; st > 0; st >>= 1) {
        if (tid < st) red[tid] += red[tid + st];
        __syncthreads();
    }
    if (tid == 0) s_rn = rsqrtf(red[0] / (float)DIM + 1e-6f);
    __syncthreads();
    const float rn = s_rn;

    const int gh = grid_sizes[1];
    const int gw = grid_sizes[2];
    const int fi = row / (gh * gw);
    const int hi = (row % (gh * gw)) / gw;
    const int wi = row % gw;

    for (int p = tid; p < DIM / 2; p += 256) {
        const int c = p & 63;
        const int pos = (c < 22) ? fi : ((c < 43) ? hi : wi);
        const float theta = freqs[pos * 64 + c];
        float sn, cs;
        sincosf(theta, &sn, &cs);
        const int idx = (p >> 6) * HDIM + 2 * c;
        const float xr = rp[idx]     * rn * g[idx];
        const float xi = rp[idx + 1] * rn * g[idx + 1];
        const float y0 = (xr * cs - xi * sn) * scale;
        const float y1 = (xr * sn + xi * cs) * scale;
        *(uint32_t*)(o + (size_t)row * DIM + idx) = pack2h(y0, y1);
    }
}

// ---------------------------------------------------------------------------
// Tensor-core flash attention, single-pass fp16 (1 MMA per matmul).
// fp32 online softmax. BQ=64, BK=64, D=128. 128 threads = 4 warps.
// Epilogue writes fp16 hi/lo for the fp16x2 O-projection.
// ---------------------------------------------------------------------------
#define QSTR 68   // u32 stride for Q/K smem rows (64 data + 4 pad)
#define VSTR 35   // u32 stride for V^T smem rows (32 data + 3 pad)

__global__ __launch_bounds__(128, 3)
void flash_f16s(const __half* __restrict__ Q, const __half* __restrict__ K,
                const __half* __restrict__ V, const int* __restrict__ seq_lens,
                __half* __restrict__ Oh, __half* __restrict__ Ol) {
    extern __shared__ uint32_t sm[];
    uint32_t* sQ = sm;
    uint32_t* sK = sQ + 64 * QSTR;
    uint32_t* sV = sK + 64 * QSTR;            // [128][VSTR] (V transposed)

    const int head = blockIdx.y;
    const int q0 = blockIdx.x * 64;
    const int tid = threadIdx.x;
    const int w = tid >> 5, lane = tid & 31;
    const int g = lane >> 2, tg = lane & 3;
    const int m0 = w * 16;
    const int seqlen = seq_lens[0];
    const int GROW = DIM / 2;

    // ---- load Q tile ----
    {
        const uint32_t* gQ = (const uint32_t*)(Q + (size_t)q0 * DIM + head * HDIM);
        for (int i = tid; i < 64 * 64; i += 128) {
            const int r = i >> 6, c = i & 63;
            sQ[r * QSTR + c] = gQ[(size_t)r * GROW + c];
        }
    }

    float m[2] = {-1e30f, -1e30f}, l[2] = {0.f, 0.f};
    float o[16][4];
#pragma unroll
    for (int n = 0; n < 16; n++)
#pragma unroll
        for (int r = 0; r < 4; r++) o[n][r] = 0.f;

    for (int k0 = 0; k0 < SEQ; k0 += 64) {
        if (k0 >= seqlen) break;
        __syncthreads();
        // ---- load K tile ----
        {
            const uint32_t* gK = (const uint32_t*)(K + (size_t)k0 * DIM + head * HDIM);
            for (int i = tid; i < 64 * 64; i += 128) {
                const int r = i >> 6, c = i & 63;
                sK[r * QSTR + c] = gK[(size_t)r * GROW + c];
            }
        }
        // ---- load V tile, transpose into [dim][kv] ----
        {
            const uint32_t* gV = (const uint32_t*)(V + (size_t)k0 * DIM + head * HDIM);
            __half* tV = (__half*)sV;
            for (int i = tid; i < 64 * 64; i += 128) {
                const int r = i >> 6, du = i & 63;
                uint32_t vv = gV[(size_t)r * GROW + du];
                __half2 v2 = *reinterpret_cast<__half2*>(&vv);
                tV[(2 * du)     * (2 * VSTR) + r] = __low2half(v2);
                tV[(2 * du + 1) * (2 * VSTR) + r] = __high2half(v2);
            }
        }
        __syncthreads();

        // ---- scores S = Q K^T (single pass) ----
        float s[8][4];
#pragma unroll
        for (int j = 0; j < 8; j++)
#pragma unroll
            for (int r = 0; r < 4; r++) s[j][r] = 0.f;

#pragma unroll
        for (int ks = 0; ks < 8; ks++) {
            uint32_t aq[4];
            const int ab = (m0 + g) * QSTR + ks * 8 + tg;
            aq[0] = sQ[ab];            aq[1] = sQ[ab + 8 * QSTR];
            aq[2] = sQ[ab + 4];        aq[3] = sQ[ab + 8 * QSTR + 4];
#pragma unroll
            for (int j = 0; j < 8; j++) {
                uint32_t bf[2];
                const int kb = (8 * j + g) * QSTR + ks * 8 + tg;
                bf[0] = sK[kb]; bf[1] = sK[kb + 4];
                MMA_F16(s[j], aq, bf);
            }
        }

        // ---- online softmax (rows m0+g and m0+g+8, warp-local) ----
        const int kv = seqlen - k0;
        float mx0 = -1e30f, mx1 = -1e30f;
#pragma unroll
        for (int j = 0; j < 8; j++) {
            const int c0 = 8 * j + 2 * tg, c1 = c0 + 1;
            if (c0 >= kv) { s[j][0] = -1e30f; s[j][2] = -1e30f; }
            if (c1 >= kv) { s[j][1] = -1e30f; s[j][3] = -1e30f; }
            mx0 = fmaxf(mx0, fmaxf(s[j][0], s[j][1]));
            mx1 = fmaxf(mx1, fmaxf(s[j][2], s[j][3]));
        }
        mx0 = fmaxf(mx0, __shfl_xor_sync(0xffffffff, mx0, 1));
        mx0 = fmaxf(mx0, __shfl_xor_sync(0xffffffff, mx0, 2));
        mx1 = fmaxf(mx1, __shfl_xor_sync(0xffffffff, mx1, 1));
        mx1 = fmaxf(mx1, __shfl_xor_sync(0xffffffff, mx1, 2));
        const float mn0 = fmaxf(m[0], mx0);
        const float mn1 = fmaxf(m[1], mx1);
        const float a0 = __expf(m[0] - mn0);
        const float a1 = __expf(m[1] - mn1);
        m[0] = mn0; m[1] = mn1;

        float sum0 = 0.f, sum1 = 0.f;
#pragma unroll
        for (int j = 0; j < 8; j++) {
            s[j][0] = __expf(s[j][0] - mn0);
            s[j][1] = __expf(s[j][1] - mn0);
            s[j][2] = __expf(s[j][2] - mn1);
            s[j][3] = __expf(s[j][3] - mn1);
            sum0 += s[j][0] + s[j][1];
            sum1 += s[j][2] + s[j][3];
        }
        sum0 += __shfl_xor_sync(0xffffffff, sum0, 1);
        sum0 += __shfl_xor_sync(0xffffffff, sum0, 2);
        sum1 += __shfl_xor_sync(0xffffffff, sum1, 1);
        sum1 += __shfl_xor_sync(0xffffffff, sum1, 2);
        l[0] = l[0] * a0 + sum0;
        l[1] = l[1] * a1 + sum1;

#pragma unroll
        for (int n = 0; n < 16; n++) {
            o[n][0] *= a0; o[n][1] *= a0;
            o[n][2] *= a1; o[n][3] *= a1;
        }

        // ---- O += P V (single pass) ----
#pragma unroll
        for (int kp = 0; kp < 4; kp++) {
            uint32_t ph[4];
            const int j0 = 2 * kp, j1 = 2 * kp + 1;
            ph[0] = pack2h(s[j0][0], s[j0][1]);
            ph[1] = pack2h(s[j0][2], s[j0][3]);
            ph[2] = pack2h(s[j1][0], s[j1][1]);
            ph[3] = pack2h(s[j1][2], s[j1][3]);
#pragma unroll
            for (int n = 0; n < 16; n++) {
                uint32_t bv[2];
                const int vb = (8 * n + g) * VSTR + kp * 8 + tg;
                bv[0] = sV[vb]; bv[1] = sV[vb + 4];
                MMA_F16(o[n], ph, bv);
            }
        }
    }

    // ---- epilogue: normalize, write fp16 hi/lo ----
    const float inv0 = 1.f / l[0];
    const float inv1 = 1.f / l[1];
    const int r0 = q0 + m0 + g;
    const int r1 = r0 + 8;
    uint32_t* oHh = (uint32_t*)(Oh);
    uint32_t* oLl = (uint32_t*)(Ol);
#pragma unroll
    for (int n = 0; n < 16; n++) {
        const int col = head * HDIM + 8 * n + 2 * tg;
        uint2 p0 = split2h(o[n][0] * inv0, o[n][1] * inv0);
        oHh[(size_t)r0 * GROW + col / 2] = p0.x;
        oLl[(size_t)r0 * GROW + col / 2] = p0.y;
        uint2 p1 = split2h(o[n][2] * inv1, o[n][3] * inv1);
        oHh[(size_t)r1 * GROW + col / 2] = p1.x;
        oLl[(size_t)r1 * GROW + col / 2] = p1.y;
    }
}

// ---------------------------------------------------------------------------
// Launch  (launch #5 = QKV GEMM — that's what ncu profiles)
// ---------------------------------------------------------------------------
extern "C" void kernel_launch(void* const* d_in, const int* in_sizes, int n_in,
                              void* d_out, int out_size) {
    const float* x         = (const float*)d_in[0];
    const int*   seq_lens  = (const int*)  d_in[1];
    const int*   grid_sz   = (const int*)  d_in[2];
    const float* freqs     = (const float*)d_in[3];
    const float* wq        = (const float*)d_in[4];
    const float* bq        = (const float*)d_in[5];
    const float* wk        = (const float*)d_in[6];
    const float* bk        = (const float*)d_in[7];
    const float* wv        = (const float*)d_in[8];
    const float* bv        = (const float*)d_in[9];
    const float* wo        = (const float*)d_in[10];
    const float* bo        = (const float*)d_in[11];
    const float* gq        = (const float*)d_in[12];
    const float* gk        = (const float*)d_in[13];
    float* out = (float*)d_out;

    float *q, *k, *v;
    cudaGetSymbolAddress((void**)&q, g_q);
    cudaGetSymbolAddress((void**)&k, g_k);
    cudaGetSymbolAddress((void**)&v, g_v);

    __half *xh, *xl, *ah, *al, *hwq, *hwk, *hwv, *hwo, *qs, *ks, *vs;
    cudaGetSymbolAddress((void**)&xh,  g_xh); cudaGetSymbolAddress((void**)&xl, g_xl);
    cudaGetSymbolAddress((void**)&ah,  g_ah); cudaGetSymbolAddress((void**)&al, g_al);
    cudaGetSymbolAddress((void**)&hwq, g_wq); cudaGetSymbolAddress((void**)&hwk, g_wk);
    cudaGetSymbolAddress((void**)&hwv, g_wv); cudaGetSymbolAddress((void**)&hwo, g_wo);
    cudaGetSymbolAddress((void**)&qs,  g_qs); cudaGetSymbolAddress((void**)&ks,  g_ks);
    cudaGetSymbolAddress((void**)&vs,  g_vs);

    const int nX = SEQ * DIM, nW = DIM * DIM;
    const int gemm_smem = 2 * STG_BYTES;   // 61440 bytes
    cudaFuncSetAttribute(gemm_f16x2_pipe,
                         cudaFuncAttributeMaxDynamicSharedMemorySize, gemm_smem);

    // launches 1-4
    split_f16<<<nX / 1024, 256>>>(x, xh, xl, nX);
    round_f16<<<nW / 1024, 256>>>(wq, hwq, nW);
    round_f16<<<nW / 1024, 256>>>(wk, hwk, nW);
    round_f16<<<nW / 1024, 256>>>(wv, hwv, nW);

    // launch 5: fused QKV GEMM (profiled by ncu)
    GemmF16Batch qkv;
    qkv.B[0] = hwq; qkv.bias[0] = bq; qkv.C[0] = q;
    qkv.B[1] = hwk; qkv.bias[1] = bk; qkv.C[1] = k;
    qkv.B[2] = hwv; qkv.bias[2] = bv; qkv.C[2] = v;
    gemm_f16x2_pipe<<<dim3(DIM / 128, SEQ / 128, 3), 256, gemm_smem>>>(
        xh, xl, qkv, SEQ, DIM, DIM);

    round_f16<<<nW / 1024, 256>>>(wo, hwo, nW);

    const float scale = 0.08838834764831845f;   // 1/sqrt(128)
    norm_rope_pack<<<SEQ, 256>>>(q, gq, freqs, grid_sz, qs, scale);
    norm_rope_pack<<<SEQ, 256>>>(k, gk, freqs, grid_sz, ks, 1.0f);
    round_f16<<<nX / 1024, 256>>>(v, vs, nX);

    const size_t fl_smem = (size_t)(2 * 64 * QSTR + 128 * VSTR) * sizeof(uint32_t);
    cudaFuncSetAttribute(flash_f16s, cudaFuncAttributeMaxDynamicSharedMemorySize, (int)fl_smem);
    flash_f16s<<<dim3(SEQ / 64, NHEADS), 128, fl_smem>>>(qs, ks, vs,
                                                         seq_lens, ah, al);

    GemmF16Batch ob;
    ob.B[0] = hwo; ob.bias[0] = bo; ob.C[0] = out;
    ob.B[1] = hwo; ob.bias[1] = bo; ob.C[1] = out;
    ob.B[2] = hwo; ob.bias[2] = bo; ob.C[2] = out;
    gemm_f16x2_pipe<<<dim3(DIM / 128, SEQ / 128, 1), 256, gemm_smem>>>(
        ah, al, ob, SEQ, DIM, DIM);
}

// round 13
// speedup vs baseline: 5.0440x; 1.3245x over previous
#include <cuda_runtime.h>
#include <cuda_fp16.h>
#include <math.h>
#include <stdint.h>

#define DIM    3072
#define NHEADS 24
#define HDIM   128
#define SEQ    2304

// ---------------------------------------------------------------------------
// Scratch (allocation-free: __device__ globals)
// ---------------------------------------------------------------------------
__device__ float g_q[SEQ * DIM];
__device__ float g_k[SEQ * DIM];
__device__ float g_v[SEQ * DIM];

__device__ __half g_xs[SEQ * DIM];                      // x single fp16
__device__ __half g_as[SEQ * DIM];                      // attn single fp16
__device__ __half g_wq[DIM * DIM], g_wk[DIM * DIM];     // weights single fp16
__device__ __half g_wv[DIM * DIM], g_wo[DIM * DIM];
__device__ __half g_qs[SEQ * DIM];                      // Q single fp16
__device__ __half g_ks[SEQ * DIM];                      // K single fp16
__device__ __half g_vs[SEQ * DIM];                      // V single fp16

__device__ __forceinline__ uint32_t pack2h(float a, float b) {
    __half2 h = __floats2half2_rn(a, b);
    return *reinterpret_cast<uint32_t*>(&h);
}

__device__ __forceinline__ void cp16(uint32_t saddr, const void* gptr) {
    asm volatile("cp.async.cg.shared.global [%0], [%1], 16;"
                 :: "r"(saddr), "l"(gptr));
}

#define MMA_F16(d, a, b)                                                      \
    asm volatile("mma.sync.aligned.m16n8k16.row.col.f32.f16.f16.f32 "         \
                 "{%0,%1,%2,%3}, {%4,%5,%6,%7}, {%8,%9}, {%0,%1,%2,%3};"      \
                 : "+f"(d[0]), "+f"(d[1]), "+f"(d[2]), "+f"(d[3])             \
                 : "r"(a[0]), "r"(a[1]), "r"(a[2]), "r"(a[3]),                \
                   "r"(b[0]), "r"(b[1]))

// ---------------------------------------------------------------------------
// fp32 -> fp16 (round-to-nearest).
// ---------------------------------------------------------------------------
__global__ __launch_bounds__(256)
void round_f16(const float* __restrict__ in, __half* __restrict__ out, int n) {
    int i = (blockIdx.x * 256 + threadIdx.x) * 4;
    if (i + 3 >= n) return;
    float4 v = *(const float4*)(in + i);
    *(uint2*)(out + i) = make_uint2(pack2h(v.x, v.y), pack2h(v.z, v.w));
}

// ---------------------------------------------------------------------------
// Single-pass fp16 GEMM (NT): C = A . B^T + bias, fp32 accum.
// BM=BN=128, BK=32, 256 threads = 8 warps (2M x 4N), cp.async 2-stage.
// ---------------------------------------------------------------------------
#define SSTR 20                        // u32 per smem row (16 data + 4 pad)
#define ARR_U32 (128 * SSTR)
#define ARR_BYTES (ARR_U32 * 4)        // 10240
#define STG_U32 (2 * ARR_U32)          // A, B
#define STG_BYTES (STG_U32 * 4)        // 20480

struct GemmF16Batch {
    const __half* B[3];
    const float*  bias[3];
    float*        C[3];
};

__global__ __launch_bounds__(256, 2)
void gemm_f16_pipe(const __half* __restrict__ A,
                   GemmF16Batch batch, int M, int N, int K) {
    extern __shared__ uint32_t smem[];
    const uint32_t sbase = (uint32_t)__cvta_generic_to_shared(smem);

    const __half* __restrict__ B = batch.B[blockIdx.z];
    const float* __restrict__ bias = batch.bias[blockIdx.z];
    float* __restrict__ C = batch.C[blockIdx.z];

    const int bm = blockIdx.y * 128, bn = blockIdx.x * 128;
    const int tid = threadIdx.x;
    const int w = tid >> 5, lane = tid & 31;
    const int wm = w & 1, wn = w >> 1;
    const int g = lane >> 2, tg = lane & 3;

    float acc[4][4][4];
#pragma unroll
    for (int mi = 0; mi < 4; mi++)
#pragma unroll
        for (int ni = 0; ni < 4; ni++)
#pragma unroll
            for (int r = 0; r < 4; r++) acc[mi][ni][r] = 0.f;

    // loader: 1024 16B chunks/stage (A 512, B 512), 4 per thread
    auto issue = [&](int kt, int stage) {
        const uint32_t sb = sbase + (uint32_t)stage * STG_BYTES;
#pragma unroll
        for (int i = 0; i < 4; i++) {
            const int c = tid + i * 256;
            const int arr = c >> 9;
            const int cid = c & 511;
            const int r = cid >> 2, q = cid & 3;
            const uint32_t dst = sb + arr * ARR_BYTES + (r * SSTR + q * 4) * 4;
            const __half* src = (arr == 0)
                ? A + (size_t)(bm + r) * K + kt + q * 8
                : B + (size_t)(bn + r) * K + kt + q * 8;
            cp16(dst, src);
        }
    };

    const int ntiles = K / 32;
    issue(0, 0);
    asm volatile("cp.async.commit_group;");

    for (int t = 0; t < ntiles; t++) {
        if (t + 1 < ntiles) issue((t + 1) * 32, (t + 1) & 1);
        asm volatile("cp.async.commit_group;");
        asm volatile("cp.async.wait_group 1;");
        __syncthreads();

        const uint32_t* sA = smem + (t & 1) * STG_U32;
        const uint32_t* sB = sA + ARR_U32;

#pragma unroll
        for (int ks = 0; ks < 2; ks++) {
            const int kb = ks * 8;
            uint32_t af[4][4], bf[4][2];
#pragma unroll
            for (int mi = 0; mi < 4; mi++) {
                const int r = wm * 64 + mi * 16 + g;
                af[mi][0] = sA[r * SSTR + kb + tg];
                af[mi][1] = sA[(r + 8) * SSTR + kb + tg];
                af[mi][2] = sA[r * SSTR + kb + tg + 4];
                af[mi][3] = sA[(r + 8) * SSTR + kb + tg + 4];
            }
#pragma unroll
            for (int ni = 0; ni < 4; ni++) {
                const int c = wn * 32 + ni * 8 + g;
                bf[ni][0] = sB[c * SSTR + kb + tg];
                bf[ni][1] = sB[c * SSTR + kb + tg + 4];
            }
#pragma unroll
            for (int mi = 0; mi < 4; mi++)
#pragma unroll
                for (int ni = 0; ni < 4; ni++)
                    MMA_F16(acc[mi][ni], af[mi], bf[ni]);
        }
        __syncthreads();
    }

#pragma unroll
    for (int mi = 0; mi < 4; mi++)
#pragma unroll
        for (int ni = 0; ni < 4; ni++) {
            const int r = bm + wm * 64 + mi * 16 + g;
            const int c = bn + wn * 32 + ni * 8 + tg * 2;
            const float b0 = bias[c], b1 = bias[c + 1];
            C[(size_t)r * N + c]           = acc[mi][ni][0] + b0;
            C[(size_t)r * N + c + 1]       = acc[mi][ni][1] + b1;
            C[(size_t)(r + 8) * N + c]     = acc[mi][ni][2] + b0;
            C[(size_t)(r + 8) * N + c + 1] = acc[mi][ni][3] + b1;
        }
}

// ---------------------------------------------------------------------------
// Fused fp32 RMSNorm + 3-axis RoPE + scale -> single fp16 output.
// ---------------------------------------------------------------------------
__global__ __launch_bounds__(256)
void norm_rope_pack(const float* __restrict__ buf, const float* __restrict__ g,
                    const float* __restrict__ freqs,
                    const int* __restrict__ grid_sizes,
                    __half* __restrict__ o, float scale) {
    __shared__ float red[256];
    __shared__ float s_rn;
    const int row = blockIdx.x;
    const int tid = threadIdx.x;
    const float* rp = buf + (size_t)row * DIM;

    float ss = 0.f;
    for (int i = tid; i < DIM; i += 256) { float v = rp[i]; ss += v * v; }
    red[tid] = ss;
    __syncthreads();
#pragma unroll
    for (int st = 128; st > 0; st >>= 1) {
        if (tid < st) red[tid] += red[tid + st];
        __syncthreads();
    }
    if (tid == 0) s_rn = rsqrtf(red[0] / (float)DIM + 1e-6f);
    __syncthreads();
    const float rn = s_rn;

    const int gh = grid_sizes[1];
    const int gw = grid_sizes[2];
    const int fi = row / (gh * gw);
    const int hi = (row % (gh * gw)) / gw;
    const int wi = row % gw;

    for (int p = tid; p < DIM / 2; p += 256) {
        const int c = p & 63;
        const int pos = (c < 22) ? fi : ((c < 43) ? hi : wi);
        const float theta = freqs[pos * 64 + c];
        float sn, cs;
        sincosf(theta, &sn, &cs);
        const int idx = (p >> 6) * HDIM + 2 * c;
        const float xr = rp[idx]     * rn * g[idx];
        const float xi = rp[idx + 1] * rn * g[idx + 1];
        const float y0 = (xr * cs - xi * sn) * scale;
        const float y1 = (xr * sn + xi * cs) * scale;
        *(uint32_t*)(o + (size_t)row * DIM + idx) = pack2h(y0, y1);
    }
}

// ---------------------------------------------------------------------------
// Tensor-core flash attention, single-pass fp16 (unchanged math from R12);
// epilogue now writes single fp16 (feeds single-pass O-projection).
// ---------------------------------------------------------------------------
#define QSTR 68
#define VSTR 35

__global__ __launch_bounds__(128, 3)
void flash_f16s(const __half* __restrict__ Q, const __half* __restrict__ K,
                const __half* __restrict__ V, const int* __restrict__ seq_lens,
                __half* __restrict__ O) {
    extern __shared__ uint32_t sm[];
    uint32_t* sQ = sm;
    uint32_t* sK = sQ + 64 * QSTR;
    uint32_t* sV = sK + 64 * QSTR;            // [128][VSTR] (V transposed)

    const int head = blockIdx.y;
    const int q0 = blockIdx.x * 64;
    const int tid = threadIdx.x;
    const int w = tid >> 5, lane = tid & 31;
    const int g = lane >> 2, tg = lane & 3;
    const int m0 = w * 16;
    const int seqlen = seq_lens[0];
    const int GROW = DIM / 2;

    {
        const uint32_t* gQ = (const uint32_t*)(Q + (size_t)q0 * DIM + head * HDIM);
        for (int i = tid; i < 64 * 64; i += 128) {
            const int r = i >> 6, c = i & 63;
            sQ[r * QSTR + c] = gQ[(size_t)r * GROW + c];
        }
    }

    float m[2] = {-1e30f, -1e30f}, l[2] = {0.f, 0.f};
    float o[16][4];
#pragma unroll
    for (int n = 0; n < 16; n++)
#pragma unroll
        for (int r = 0; r < 4; r++) o[n][r] = 0.f;

    for (int k0 = 0; k0 < SEQ; k0 += 64) {
        if (k0 >= seqlen) break;
        __syncthreads();
        {
            const uint32_t* gK = (const uint32_t*)(K + (size_t)k0 * DIM + head * HDIM);
            for (int i = tid; i < 64 * 64; i += 128) {
                const int r = i >> 6, c = i & 63;
                sK[r * QSTR + c] = gK[(size_t)r * GROW + c];
            }
        }
        {
            const uint32_t* gV = (const uint32_t*)(V + (size_t)k0 * DIM + head * HDIM);
            __half* tV = (__half*)sV;
            for (int i = tid; i < 64 * 64; i += 128) {
                const int r = i >> 6, du = i & 63;
                uint32_t vv = gV[(size_t)r * GROW + du];
                __half2 v2 = *reinterpret_cast<__half2*>(&vv);
                tV[(2 * du)     * (2 * VSTR) + r] = __low2half(v2);
                tV[(2 * du + 1) * (2 * VSTR) + r] = __high2half(v2);
            }
        }
        __syncthreads();

        float s[8][4];
#pragma unroll
        for (int j = 0; j < 8; j++)
#pragma unroll
            for (int r = 0; r < 4; r++) s[j][r] = 0.f;

#pragma unroll
        for (int ks = 0; ks < 8; ks++) {
            uint32_t aq[4];
            const int ab = (m0 + g) * QSTR + ks * 8 + tg;
            aq[0] = sQ[ab];            aq[1] = sQ[ab + 8 * QSTR];
            aq[2] = sQ[ab + 4];        aq[3] = sQ[ab + 8 * QSTR + 4];
#pragma unroll
            for (int j = 0; j < 8; j++) {
                uint32_t bf[2];
                const int kb = (8 * j + g) * QSTR + ks * 8 + tg;
                bf[0] = sK[kb]; bf[1] = sK[kb + 4];
                MMA_F16(s[j], aq, bf);
            }
        }

        const int kv = seqlen - k0;
        float mx0 = -1e30f, mx1 = -1e30f;
#pragma unroll
        for (int j = 0; j < 8; j++) {
            const int c0 = 8 * j + 2 * tg, c1 = c0 + 1;
            if (c0 >= kv) { s[j][0] = -1e30f; s[j][2] = -1e30f; }
            if (c1 >= kv) { s[j][1] = -1e30f; s[j][3] = -1e30f; }
            mx0 = fmaxf(mx0, fmaxf(s[j][0], s[j][1]));
            mx1 = fmaxf(mx1, fmaxf(s[j][2], s[j][3]));
        }
        mx0 = fmaxf(mx0, __shfl_xor_sync(0xffffffff, mx0, 1));
        mx0 = fmaxf(mx0, __shfl_xor_sync(0xffffffff, mx0, 2));
        mx1 = fmaxf(mx1, __shfl_xor_sync(0xffffffff, mx1, 1));
        mx1 = fmaxf(mx1, __shfl_xor_sync(0xffffffff, mx1, 2));
        const float mn0 = fmaxf(m[0], mx0);
        const float mn1 = fmaxf(m[1], mx1);
        const float a0 = __expf(m[0] - mn0);
        const float a1 = __expf(m[1] - mn1);
        m[0] = mn0; m[1] = mn1;

        float sum0 = 0.f, sum1 = 0.f;
#pragma unroll
        for (int j = 0; j < 8; j++) {
            s[j][0] = __expf(s[j][0] - mn0);
            s[j][1] = __expf(s[j][1] - mn0);
            s[j][2] = __expf(s[j][2] - mn1);
            s[j][3] = __expf(s[j][3] - mn1);
            sum0 += s[j][0] + s[j][1];
            sum1 += s[j][2] + s[j][3];
        }
        sum0 += __shfl_xor_sync(0xffffffff, sum0, 1);
        sum0 += __shfl_xor_sync(0xffffffff, sum0, 2);
        sum1 += __shfl_xor_sync(0xffffffff, sum1, 1);
        sum1 += __shfl_xor_sync(0xffffffff, sum1, 2);
        l[0] = l[0] * a0 + sum0;
        l[1] = l[1] * a1 + sum1;

#pragma unroll
        for (int n = 0; n < 16; n++) {
            o[n][0] *= a0; o[n][1] *= a0;
            o[n][2] *= a1; o[n][3] *= a1;
        }

#pragma unroll
        for (int kp = 0; kp < 4; kp++) {
            uint32_t ph[4];
            const int j0 = 2 * kp, j1 = 2 * kp + 1;
            ph[0] = pack2h(s[j0][0], s[j0][1]);
            ph[1] = pack2h(s[j0][2], s[j0][3]);
            ph[2] = pack2h(s[j1][0], s[j1][1]);
            ph[3] = pack2h(s[j1][2], s[j1][3]);
#pragma unroll
            for (int n = 0; n < 16; n++) {
                uint32_t bv[2];
                const int vb = (8 * n + g) * VSTR + kp * 8 + tg;
                bv[0] = sV[vb]; bv[1] = sV[vb + 4];
                MMA_F16(o[n], ph, bv);
            }
        }
    }

    // ---- epilogue: normalize, write single fp16 ----
    const float inv0 = 1.f / l[0];
    const float inv1 = 1.f / l[1];
    const int r0 = q0 + m0 + g;
    const int r1 = r0 + 8;
    uint32_t* oO = (uint32_t*)(O);
#pragma unroll
    for (int n = 0; n < 16; n++) {
        const int col = head * HDIM + 8 * n + 2 * tg;
        oO[(size_t)r0 * GROW + col / 2] = pack2h(o[n][0] * inv0, o[n][1] * inv0);
        oO[(size_t)r1 * GROW + col / 2] = pack2h(o[n][2] * inv1, o[n][3] * inv1);
    }
}

// ---------------------------------------------------------------------------
// Launch  (launch #5 = QKV GEMM — that's what ncu profiles)
// ---------------------------------------------------------------------------
extern "C" void kernel_launch(void* const* d_in, const int* in_sizes, int n_in,
                              void* d_out, int out_size) {
    const float* x         = (const float*)d_in[0];
    const int*   seq_lens  = (const int*)  d_in[1];
    const int*   grid_sz   = (const int*)  d_in[2];
    const float* freqs     = (const float*)d_in[3];
    const float* wq        = (const float*)d_in[4];
    const float* bq        = (const float*)d_in[5];
    const float* wk        = (const float*)d_in[6];
    const float* bk        = (const float*)d_in[7];
    const float* wv        = (const float*)d_in[8];
    const float* bv        = (const float*)d_in[9];
    const float* wo        = (const float*)d_in[10];
    const float* bo        = (const float*)d_in[11];
    const float* gq        = (const float*)d_in[12];
    const float* gk        = (const float*)d_in[13];
    float* out = (float*)d_out;

    float *q, *k, *v;
    cudaGetSymbolAddress((void**)&q, g_q);
    cudaGetSymbolAddress((void**)&k, g_k);
    cudaGetSymbolAddress((void**)&v, g_v);

    __half *xs, *as, *hwq, *hwk, *hwv, *hwo, *qs, *ks, *vs;
    cudaGetSymbolAddress((void**)&xs,  g_xs); cudaGetSymbolAddress((void**)&as,  g_as);
    cudaGetSymbolAddress((void**)&hwq, g_wq); cudaGetSymbolAddress((void**)&hwk, g_wk);
    cudaGetSymbolAddress((void**)&hwv, g_wv); cudaGetSymbolAddress((void**)&hwo, g_wo);
    cudaGetSymbolAddress((void**)&qs,  g_qs); cudaGetSymbolAddress((void**)&ks,  g_ks);
    cudaGetSymbolAddress((void**)&vs,  g_vs);

    const int nX = SEQ * DIM, nW = DIM * DIM;
    const int gemm_smem = 2 * STG_BYTES;   // 40960 bytes
    cudaFuncSetAttribute(gemm_f16_pipe,
                         cudaFuncAttributeMaxDynamicSharedMemorySize, gemm_smem);

    // launches 1-4
    round_f16<<<nX / 1024, 256>>>(x, xs, nX);
    round_f16<<<nW / 1024, 256>>>(wq, hwq, nW);
    round_f16<<<nW / 1024, 256>>>(wk, hwk, nW);
    round_f16<<<nW / 1024, 256>>>(wv, hwv, nW);

    // launch 5: fused QKV GEMM (profiled by ncu)
    GemmF16Batch qkv;
    qkv.B[0] = hwq; qkv.bias[0] = bq; qkv.C[0] = q;
    qkv.B[1] = hwk; qkv.bias[1] = bk; qkv.C[1] = k;
    qkv.B[2] = hwv; qkv.bias[2] = bv; qkv.C[2] = v;
    gemm_f16_pipe<<<dim3(DIM / 128, SEQ / 128, 3), 256, gemm_smem>>>(
        xs, qkv, SEQ, DIM, DIM);

    round_f16<<<nW / 1024, 256>>>(wo, hwo, nW);

    const float scale = 0.08838834764831845f;   // 1/sqrt(128)
    norm_rope_pack<<<SEQ, 256>>>(q, gq, freqs, grid_sz, qs, scale);
    norm_rope_pack<<<SEQ, 256>>>(k, gk, freqs, grid_sz, ks, 1.0f);
    round_f16<<<nX / 1024, 256>>>(v, vs, nX);

    const size_t fl_smem = (size_t)(2 * 64 * QSTR + 128 * VSTR) * sizeof(uint32_t);
    cudaFuncSetAttribute(flash_f16s, cudaFuncAttributeMaxDynamicSharedMemorySize, (int)fl_smem);
    flash_f16s<<<dim3(SEQ / 64, NHEADS), 128, fl_smem>>>(qs, ks, vs, seq_lens, as);

    GemmF16Batch ob;
    ob.B[0] = hwo; ob.bias[0] = bo; ob.C[0] = out;
    ob.B[1] = hwo; ob.bias[1] = bo; ob.C[1] = out;
    ob.B[2] = hwo; ob.bias[2] = bo; ob.C[2] = out;
    gemm_f16_pipe<<<dim3(DIM / 128, SEQ / 128, 1), 256, gemm_smem>>>(
        as, ob, SEQ, DIM, DIM);
}

// round 14
// speedup vs baseline: 6.5975x; 1.3080x over previous
#include <cuda_runtime.h>
#include <cuda_fp16.h>
#include <math.h>
#include <stdint.h>

#define DIM    3072
#define NHEADS 24
#define HDIM   128
#define SEQ    2304

// ---------------------------------------------------------------------------
// Scratch (allocation-free: __device__ globals)
// ---------------------------------------------------------------------------
__device__ float g_q[SEQ * DIM];
__device__ float g_k[SEQ * DIM];
__device__ float g_dummy[SEQ * DIM];

__device__ __half g_xs[SEQ * DIM];                      // x single fp16
__device__ __half g_as[SEQ * DIM];                      // attn single fp16
__device__ __half g_wq[DIM * DIM], g_wk[DIM * DIM];     // weights single fp16
__device__ __half g_wv[DIM * DIM], g_wo[DIM * DIM];
__device__ __half g_qs[SEQ * DIM];                      // Q single fp16
__device__ __half g_ks[SEQ * DIM];                      // K single fp16
__device__ __half g_vs[SEQ * DIM];                      // V single fp16 (GEMM-written)

__device__ __forceinline__ uint32_t pack2h(float a, float b) {
    __half2 h = __floats2half2_rn(a, b);
    return *reinterpret_cast<uint32_t*>(&h);
}

__device__ __forceinline__ void cp16(uint32_t saddr, const void* gptr) {
    asm volatile("cp.async.cg.shared.global [%0], [%1], 16;"
                 :: "r"(saddr), "l"(gptr));
}

#define MMA_F16(d, a, b)                                                      \
    asm volatile("mma.sync.aligned.m16n8k16.row.col.f32.f16.f16.f32 "         \
                 "{%0,%1,%2,%3}, {%4,%5,%6,%7}, {%8,%9}, {%0,%1,%2,%3};"      \
                 : "+f"(d[0]), "+f"(d[1]), "+f"(d[2]), "+f"(d[3])             \
                 : "r"(a[0]), "r"(a[1]), "r"(a[2]), "r"(a[3]),                \
                   "r"(b[0]), "r"(b[1]))

// ---------------------------------------------------------------------------
// fp32 -> fp16 (round-to-nearest).
// ---------------------------------------------------------------------------
__global__ __launch_bounds__(256)
void round_f16(const float* __restrict__ in, __half* __restrict__ out, int n) {
    int i = (blockIdx.x * 256 + threadIdx.x) * 4;
    if (i + 3 >= n) return;
    float4 v = *(const float4*)(in + i);
    *(uint2*)(out + i) = make_uint2(pack2h(v.x, v.y), pack2h(v.z, v.w));
}

// ---------------------------------------------------------------------------
// Single-pass fp16 GEMM (NT): C = A . B^T + bias, fp32 accum.
// Optional fp16 output (Ch[z] != nullptr -> write half instead of float).
// BM=BN=128, BK=32, 256 threads = 8 warps (2M x 4N), cp.async 2-stage.
// ---------------------------------------------------------------------------
#define SSTR 20                        // u32 per smem row (16 data + 4 pad)
#define ARR_U32 (128 * SSTR)
#define ARR_BYTES (ARR_U32 * 4)        // 10240
#define STG_U32 (2 * ARR_U32)          // A, B
#define STG_BYTES (STG_U32 * 4)        // 20480

struct GemmF16Batch {
    const __half* B[3];
    const float*  bias[3];
    float*        C[3];
    __half*       Ch[3];
};

__global__ __launch_bounds__(256, 2)
void gemm_f16_pipe(const __half* __restrict__ A,
                   GemmF16Batch batch, int M, int N, int K) {
    extern __shared__ uint32_t smem[];
    const uint32_t sbase = (uint32_t)__cvta_generic_to_shared(smem);

    const __half* __restrict__ B = batch.B[blockIdx.z];
    const float* __restrict__ bias = batch.bias[blockIdx.z];
    float* __restrict__ C = batch.C[blockIdx.z];
    __half* __restrict__ Ch = batch.Ch[blockIdx.z];

    const int bm = blockIdx.y * 128, bn = blockIdx.x * 128;
    const int tid = threadIdx.x;
    const int w = tid >> 5, lane = tid & 31;
    const int wm = w & 1, wn = w >> 1;
    const int g = lane >> 2, tg = lane & 3;

    float acc[4][4][4];
#pragma unroll
    for (int mi = 0; mi < 4; mi++)
#pragma unroll
        for (int ni = 0; ni < 4; ni++)
#pragma unroll
            for (int r = 0; r < 4; r++) acc[mi][ni][r] = 0.f;

    auto issue = [&](int kt, int stage) {
        const uint32_t sb = sbase + (uint32_t)stage * STG_BYTES;
#pragma unroll
        for (int i = 0; i < 4; i++) {
            const int c = tid + i * 256;
            const int arr = c >> 9;
            const int cid = c & 511;
            const int r = cid >> 2, q = cid & 3;
            const uint32_t dst = sb + arr * ARR_BYTES + (r * SSTR + q * 4) * 4;
            const __half* src = (arr == 0)
                ? A + (size_t)(bm + r) * K + kt + q * 8
                : B + (size_t)(bn + r) * K + kt + q * 8;
            cp16(dst, src);
        }
    };

    const int ntiles = K / 32;
    issue(0, 0);
    asm volatile("cp.async.commit_group;");

    for (int t = 0; t < ntiles; t++) {
        if (t + 1 < ntiles) issue((t + 1) * 32, (t + 1) & 1);
        asm volatile("cp.async.commit_group;");
        asm volatile("cp.async.wait_group 1;");
        __syncthreads();

        const uint32_t* sA = smem + (t & 1) * STG_U32;
        const uint32_t* sB = sA + ARR_U32;

#pragma unroll
        for (int ks = 0; ks < 2; ks++) {
            const int kb = ks * 8;
            uint32_t af[4][4], bf[4][2];
#pragma unroll
            for (int mi = 0; mi < 4; mi++) {
                const int r = wm * 64 + mi * 16 + g;
                af[mi][0] = sA[r * SSTR + kb + tg];
                af[mi][1] = sA[(r + 8) * SSTR + kb + tg];
                af[mi][2] = sA[r * SSTR + kb + tg + 4];
                af[mi][3] = sA[(r + 8) * SSTR + kb + tg + 4];
            }
#pragma unroll
            for (int ni = 0; ni < 4; ni++) {
                const int c = wn * 32 + ni * 8 + g;
                bf[ni][0] = sB[c * SSTR + kb + tg];
                bf[ni][1] = sB[c * SSTR + kb + tg + 4];
            }
#pragma unroll
            for (int mi = 0; mi < 4; mi++)
#pragma unroll
                for (int ni = 0; ni < 4; ni++)
                    MMA_F16(acc[mi][ni], af[mi], bf[ni]);
        }
        __syncthreads();
    }

#pragma unroll
    for (int mi = 0; mi < 4; mi++)
#pragma unroll
        for (int ni = 0; ni < 4; ni++) {
            const int r = bm + wm * 64 + mi * 16 + g;
            const int c = bn + wn * 32 + ni * 8 + tg * 2;
            const float b0 = bias[c], b1 = bias[c + 1];
            if (Ch) {
                uint32_t* dst = (uint32_t*)Ch;
                dst[((size_t)r * N + c) >> 1] =
                    pack2h(acc[mi][ni][0] + b0, acc[mi][ni][1] + b1);
                dst[((size_t)(r + 8) * N + c) >> 1] =
                    pack2h(acc[mi][ni][2] + b0, acc[mi][ni][3] + b1);
            } else {
                C[(size_t)r * N + c]           = acc[mi][ni][0] + b0;
                C[(size_t)r * N + c + 1]       = acc[mi][ni][1] + b1;
                C[(size_t)(r + 8) * N + c]     = acc[mi][ni][2] + b0;
                C[(size_t)(r + 8) * N + c + 1] = acc[mi][ni][3] + b1;
            }
        }
}

// ---------------------------------------------------------------------------
// Fused fp32 RMSNorm + 3-axis RoPE + scale -> single fp16 output.
// ---------------------------------------------------------------------------
__global__ __launch_bounds__(256)
void norm_rope_pack(const float* __restrict__ buf, const float* __restrict__ g,
                    const float* __restrict__ freqs,
                    const int* __restrict__ grid_sizes,
                    __half* __restrict__ o, float scale) {
    __shared__ float red[256];
    __shared__ float s_rn;
    const int row = blockIdx.x;
    const int tid = threadIdx.x;
    const float* rp = buf + (size_t)row * DIM;

    float ss = 0.f;
    for (int i = tid; i < DIM; i += 256) { float v = rp[i]; ss += v * v; }
    red[tid] = ss;
    __syncthreads();
#pragma unroll
    for (int st = 128; st > 0; st >>= 1) {
        if (tid < st) red[tid] += red[tid + st];
        __syncthreads();
    }
    if (tid == 0) s_rn = rsqrtf(red[0] / (float)DIM + 1e-6f);
    __syncthreads();
    const float rn = s_rn;

    const int gh = grid_sizes[1];
    const int gw = grid_sizes[2];
    const int fi = row / (gh * gw);
    const int hi = (row % (gh * gw)) / gw;
    const int wi = row % gw;

    for (int p = tid; p < DIM / 2; p += 256) {
        const int c = p & 63;
        const int pos = (c < 22) ? fi : ((c < 43) ? hi : wi);
        const float theta = freqs[pos * 64 + c];
        float sn, cs;
        sincosf(theta, &sn, &cs);
        const int idx = (p >> 6) * HDIM + 2 * c;
        const float xr = rp[idx]     * rn * g[idx];
        const float xi = rp[idx + 1] * rn * g[idx + 1];
        const float y0 = (xr * cs - xi * sn) * scale;
        const float y1 = (xr * sn + xi * cs) * scale;
        *(uint32_t*)(o + (size_t)row * DIM + idx) = pack2h(y0, y1);
    }
}

// ---------------------------------------------------------------------------
// Tensor-core flash attention, single-pass fp16.
// cp.async K/V loads; V stays ROW-MAJOR in smem, PV B-fragments via
// ldmatrix.m8n8.x2.trans (no manual transpose).
// BQ=64, BK=64, D=128. 128 threads = 4 warps.
// ---------------------------------------------------------------------------
#define FSTR 68   // u32 stride for Q/K/V smem rows (64 data + 4 pad)

__global__ __launch_bounds__(128, 3)
void flash_f16s(const __half* __restrict__ Q, const __half* __restrict__ K,
                const __half* __restrict__ V, const int* __restrict__ seq_lens,
                __half* __restrict__ O) {
    extern __shared__ uint32_t sm[];
    uint32_t* sQ = sm;
    uint32_t* sK = sQ + 64 * FSTR;
    uint32_t* sV = sK + 64 * FSTR;            // row-major [kv][dim]

    const uint32_t smb = (uint32_t)__cvta_generic_to_shared(sm);
    const uint32_t bK = smb + 64 * FSTR * 4;
    const uint32_t bV = bK + 64 * FSTR * 4;

    const int head = blockIdx.y;
    const int q0 = blockIdx.x * 64;
    const int tid = threadIdx.x;
    const int w = tid >> 5, lane = tid & 31;
    const int g = lane >> 2, tg = lane & 3;
    const int m0 = w * 16;
    const int seqlen = seq_lens[0];
    const int GROW = DIM / 2;

    // ---- load Q tile (scalar, once) ----
    {
        const uint32_t* gQ = (const uint32_t*)(Q + (size_t)q0 * DIM + head * HDIM);
        for (int i = tid; i < 64 * 64; i += 128) {
            const int r = i >> 6, c = i & 63;
            sQ[r * FSTR + c] = gQ[(size_t)r * GROW + c];
        }
    }

    float m[2] = {-1e30f, -1e30f}, l[2] = {0.f, 0.f};
    float o[16][4];
#pragma unroll
    for (int n = 0; n < 16; n++)
#pragma unroll
        for (int r = 0; r < 4; r++) o[n][r] = 0.f;

    for (int k0 = 0; k0 < SEQ; k0 += 64) {
        if (k0 >= seqlen) break;
        __syncthreads();   // prior tile's compute done before overwrite

        // ---- cp.async K and V tiles (row-major) ----
        {
            const __half* gK = K + (size_t)k0 * DIM + head * HDIM;
            const __half* gV = V + (size_t)k0 * DIM + head * HDIM;
#pragma unroll
            for (int i = 0; i < 8; i++) {
                const int c = tid + i * 128;
                const int r = c >> 4, q = c & 15;
                cp16(bK + (r * FSTR + q * 4) * 4, gK + (size_t)r * DIM + q * 8);
                cp16(bV + (r * FSTR + q * 4) * 4, gV + (size_t)r * DIM + q * 8);
            }
        }
        asm volatile("cp.async.commit_group;");
        asm volatile("cp.async.wait_group 0;");
        __syncthreads();

        // ---- scores S = Q K^T (single pass) ----
        float s[8][4];
#pragma unroll
        for (int j = 0; j < 8; j++)
#pragma unroll
            for (int r = 0; r < 4; r++) s[j][r] = 0.f;

#pragma unroll
        for (int ks = 0; ks < 8; ks++) {
            uint32_t aq[4];
            const int ab = (m0 + g) * FSTR + ks * 8 + tg;
            aq[0] = sQ[ab];            aq[1] = sQ[ab + 8 * FSTR];
            aq[2] = sQ[ab + 4];        aq[3] = sQ[ab + 8 * FSTR + 4];
#pragma unroll
            for (int j = 0; j < 8; j++) {
                uint32_t bf[2];
                const int kb = (8 * j + g) * FSTR + ks * 8 + tg;
                bf[0] = sK[kb]; bf[1] = sK[kb + 4];
                MMA_F16(s[j], aq, bf);
            }
        }

        // ---- online softmax ----
        const int kv = seqlen - k0;
        float mx0 = -1e30f, mx1 = -1e30f;
#pragma unroll
        for (int j = 0; j < 8; j++) {
            const int c0 = 8 * j + 2 * tg, c1 = c0 + 1;
            if (c0 >= kv) { s[j][0] = -1e30f; s[j][2] = -1e30f; }
            if (c1 >= kv) { s[j][1] = -1e30f; s[j][3] = -1e30f; }
            mx0 = fmaxf(mx0, fmaxf(s[j][0], s[j][1]));
            mx1 = fmaxf(mx1, fmaxf(s[j][2], s[j][3]));
        }
        mx0 = fmaxf(mx0, __shfl_xor_sync(0xffffffff, mx0, 1));
        mx0 = fmaxf(mx0, __shfl_xor_sync(0xffffffff, mx0, 2));
        mx1 = fmaxf(mx1, __shfl_xor_sync(0xffffffff, mx1, 1));
        mx1 = fmaxf(mx1, __shfl_xor_sync(0xffffffff, mx1, 2));
        const float mn0 = fmaxf(m[0], mx0);
        const float mn1 = fmaxf(m[1], mx1);
        const float a0 = __expf(m[0] - mn0);
        const float a1 = __expf(m[1] - mn1);
        m[0] = mn0; m[1] = mn1;

        float sum0 = 0.f, sum1 = 0.f;
#pragma unroll
        for (int j = 0; j < 8; j++) {
            s[j][0] = __expf(s[j][0] - mn0);
            s[j][1] = __expf(s[j][1] - mn0);
            s[j][2] = __expf(s[j][2] - mn1);
            s[j][3] = __expf(s[j][3] - mn1);
            sum0 += s[j][0] + s[j][1];
            sum1 += s[j][2] + s[j][3];
        }
        sum0 += __shfl_xor_sync(0xffffffff, sum0, 1);
        sum0 += __shfl_xor_sync(0xffffffff, sum0, 2);
        sum1 += __shfl_xor_sync(0xffffffff, sum1, 1);
        sum1 += __shfl_xor_sync(0xffffffff, sum1, 2);
        l[0] = l[0] * a0 + sum0;
        l[1] = l[1] * a1 + sum1;

#pragma unroll
        for (int n = 0; n < 16; n++) {
            o[n][0] *= a0; o[n][1] *= a0;
            o[n][2] *= a1; o[n][3] *= a1;
        }

        // ---- O += P V  (B-fragments via ldmatrix.x2.trans on row-major V) ----
#pragma unroll
        for (int kp = 0; kp < 4; kp++) {
            uint32_t ph[4];
            const int j0 = 2 * kp, j1 = 2 * kp + 1;
            ph[0] = pack2h(s[j0][0], s[j0][1]);
            ph[1] = pack2h(s[j0][2], s[j0][3]);
            ph[2] = pack2h(s[j1][0], s[j1][1]);
            ph[3] = pack2h(s[j1][2], s[j1][3]);
            // lane (i & 15) supplies the address of V row kp*16 + (i&15)
            const uint32_t vrow = bV + (uint32_t)(kp * 16 + (lane & 15)) * (FSTR * 4);
#pragma unroll
            for (int n2 = 0; n2 < 16; n2++) {
                uint32_t bv[2];
                asm volatile(
                    "ldmatrix.sync.aligned.m8n8.x2.trans.shared.b16 {%0,%1}, [%2];"
                    : "=r"(bv[0]), "=r"(bv[1])
                    : "r"(vrow + n2 * 16));
                MMA_F16(o[n2], ph, bv);
            }
        }
    }

    // ---- epilogue: normalize, write single fp16 ----
    const float inv0 = 1.f / l[0];
    const float inv1 = 1.f / l[1];
    const int r0 = q0 + m0 + g;
    const int r1 = r0 + 8;
    uint32_t* oO = (uint32_t*)(O);
#pragma unroll
    for (int n = 0; n < 16; n++) {
        const int col = head * HDIM + 8 * n + 2 * tg;
        oO[(size_t)r0 * GROW + col / 2] = pack2h(o[n][0] * inv0, o[n][1] * inv0);
        oO[(size_t)r1 * GROW + col / 2] = pack2h(o[n][2] * inv1, o[n][3] * inv1);
    }
}

// ---------------------------------------------------------------------------
// Launch  (launch #5 = QKV GEMM — that's what ncu profiles)
// ---------------------------------------------------------------------------
extern "C" void kernel_launch(void* const* d_in, const int* in_sizes, int n_in,
                              void* d_out, int out_size) {
    const float* x         = (const float*)d_in[0];
    const int*   seq_lens  = (const int*)  d_in[1];
    const int*   grid_sz   = (const int*)  d_in[2];
    const float* freqs     = (const float*)d_in[3];
    const float* wq        = (const float*)d_in[4];
    const float* bq        = (const float*)d_in[5];
    const float* wk        = (const float*)d_in[6];
    const float* bk        = (const float*)d_in[7];
    const float* wv        = (const float*)d_in[8];
    const float* bv        = (const float*)d_in[9];
    const float* wo        = (const float*)d_in[10];
    const float* bo        = (const float*)d_in[11];
    const float* gq        = (const float*)d_in[12];
    const float* gk        = (const float*)d_in[13];
    float* out = (float*)d_out;

    float *q, *k, *dummy;
    cudaGetSymbolAddress((void**)&q, g_q);
    cudaGetSymbolAddress((void**)&k, g_k);
    cudaGetSymbolAddress((void**)&dummy, g_dummy);

    __half *xs, *as, *hwq, *hwk, *hwv, *hwo, *qs, *ks, *vs;
    cudaGetSymbolAddress((void**)&xs,  g_xs); cudaGetSymbolAddress((void**)&as,  g_as);
    cudaGetSymbolAddress((void**)&hwq, g_wq); cudaGetSymbolAddress((void**)&hwk, g_wk);
    cudaGetSymbolAddress((void**)&hwv, g_wv); cudaGetSymbolAddress((void**)&hwo, g_wo);
    cudaGetSymbolAddress((void**)&qs,  g_qs); cudaGetSymbolAddress((void**)&ks,  g_ks);
    cudaGetSymbolAddress((void**)&vs,  g_vs);

    const int nX = SEQ * DIM, nW = DIM * DIM;
    const int gemm_smem = 2 * STG_BYTES;   // 40960 bytes
    cudaFuncSetAttribute(gemm_f16_pipe,
                         cudaFuncAttributeMaxDynamicSharedMemorySize, gemm_smem);

    // launches 1-4
    round_f16<<<nX / 1024, 256>>>(x, xs, nX);
    round_f16<<<nW / 1024, 256>>>(wq, hwq, nW);
    round_f16<<<nW / 1024, 256>>>(wk, hwk, nW);
    round_f16<<<nW / 1024, 256>>>(wv, hwv, nW);

    // launch 5: fused QKV GEMM (profiled by ncu); V written directly as fp16
    GemmF16Batch qkv;
    qkv.B[0] = hwq; qkv.bias[0] = bq; qkv.C[0] = q;     qkv.Ch[0] = nullptr;
    qkv.B[1] = hwk; qkv.bias[1] = bk; qkv.C[1] = k;     qkv.Ch[1] = nullptr;
    qkv.B[2] = hwv; qkv.bias[2] = bv; qkv.C[2] = dummy; qkv.Ch[2] = vs;
    gemm_f16_pipe<<<dim3(DIM / 128, SEQ / 128, 3), 256, gemm_smem>>>(
        xs, qkv, SEQ, DIM, DIM);

    round_f16<<<nW / 1024, 256>>>(wo, hwo, nW);

    const float scale = 0.08838834764831845f;   // 1/sqrt(128)
    norm_rope_pack<<<SEQ, 256>>>(q, gq, freqs, grid_sz, qs, scale);
    norm_rope_pack<<<SEQ, 256>>>(k, gk, freqs, grid_sz, ks, 1.0f);

    const size_t fl_smem = (size_t)(3 * 64 * FSTR) * sizeof(uint32_t);  // 52224
    cudaFuncSetAttribute(flash_f16s, cudaFuncAttributeMaxDynamicSharedMemorySize, (int)fl_smem);
    flash_f16s<<<dim3(SEQ / 64, NHEADS), 128, fl_smem>>>(qs, ks, vs, seq_lens, as);

    GemmF16Batch ob;
    ob.B[0] = hwo; ob.bias[0] = bo; ob.C[0] = out; ob.Ch[0] = nullptr;
    ob.B[1] = hwo; ob.bias[1] = bo; ob.C[1] = out; ob.Ch[1] = nullptr;
    ob.B[2] = hwo; ob.bias[2] = bo; ob.C[2] = out; ob.Ch[2] = nullptr;
    gemm_f16_pipe<<<dim3(DIM / 128, SEQ / 128, 1), 256, gemm_smem>>>(
        as, ob, SEQ, DIM, DIM);
}